// round 6
// baseline (speedup 1.0000x reference)
#include <cuda_runtime.h>
#include <cuda_fp16.h>
#include <cstdint>

#define BB   8
#define NN   8192
#define EE   262144
#define FIN  64
#define HH   128
#define FOUT 32
#define TOT  (BB*NN)   // 65536 rows total
#define CAP  256       // max edges per row bucket (deg ~ Poisson(32))

typedef unsigned long long ull;
typedef unsigned int uint;

// ---------------- device scratch (no allocations allowed) ----------------
__device__ float g_h0[(size_t)TOT*HH];
__device__ uint  g_hcp[(size_t)TOT*(HH/2)];   // hc as fp16x2 pairs
__device__ float g_h1[(size_t)TOT*HH];
__device__ float g_h2[(size_t)TOT*HH];
__device__ int   g_cnt[TOT];
__device__ uint  g_bkt[(size_t)TOT*CAP];      // packed edge: [fp16 val | 16-bit col]
__device__ float g_stat[6*HH];                // [stage][sum|sumsq][H], stages 0..2
__device__ float g_M[HH*HH];                  // W02 @ Wc
__device__ float g_Wa[HH*HH];
__device__ float g_ba[HH];
__device__ float g_Wb[HH*HH];
__device__ float g_bb[HH];
__device__ float g_Wo[HH*FOUT];
__device__ float g_bo[FOUT];

__device__ __forceinline__ ull dup_f32(float a) {
    ull d; asm("mov.b64 %0, {%1, %1};" : "=l"(d) : "f"(a)); return d;
}
__device__ __forceinline__ void fma2(ull& acc, ull a, ull b) {
    asm("fma.rn.f32x2 %0, %1, %2, %0;" : "+l"(acc) : "l"(a), "l"(b));
}
__device__ __forceinline__ void unpack2(float& lo, float& hi, ull v) {
    asm("mov.b64 {%0, %1}, %2;" : "=f"(lo), "=f"(hi) : "l"(v));
}
__device__ __forceinline__ float2 h2f(uint p) {
    return __half22float2(*reinterpret_cast<__half2*>(&p));
}

// ---------------- init: zero accumulators, seed fused bias for Wa ----------------
__global__ void init_kernel(const float* __restrict__ b02, const float* __restrict__ Wc,
                            const float* __restrict__ bc)
{
    int gid = blockIdx.x * 256 + threadIdx.x;
    if (gid < TOT) g_cnt[gid] = 0;
    if (gid < 6*HH) g_stat[gid] = 0.f;
    if (blockIdx.x == gridDim.x - 1 && threadIdx.x < HH) {
        int k = threadIdx.x;
        float s = bc[k];
        #pragma unroll 4
        for (int f = 0; f < HH; f++) s += b02[f] * Wc[f*HH + k];
        g_ba[k] = s;          // (b02 @ Wc + bc); fold adds t0 @ M
    }
}

// ---------------- M = W02 @ Wc (tiny) ----------------
__global__ void mm128_kernel(const float* __restrict__ W02, const float* __restrict__ Wc)
{
    __shared__ float row[HH];
    int f = blockIdx.x, k = threadIdx.x;
    row[k] = W02[f*HH + k];
    __syncthreads();
    float s = 0.f;
    #pragma unroll 4
    for (int j = 0; j < HH; j++) s = fmaf(row[j], Wc[j*HH + k], s);
    g_M[f*HH + k] = s;
}

// ---------------- BN fold: stats -> affine, applied to weight + bias ----------------
__global__ void fold_kernel(const float* __restrict__ bnw, const float* __restrict__ bnb,
                            int stage, const float* __restrict__ Msrc,
                            float* __restrict__ Wdst,
                            const float* __restrict__ bias_in, float* __restrict__ bias_out,
                            int NC)
{
    __shared__ float ss[HH], st[HH];
    int tid = threadIdx.x;    // 128
    {
        float cnt = (float)TOT;
        float sum = g_stat[stage*2*HH + tid];
        float sq  = g_stat[stage*2*HH + HH + tid];
        float m = sum / cnt;
        float v = sq / cnt - m*m;
        float inv = rsqrtf(v + 1e-5f);
        float s = bnw[tid] * inv;
        ss[tid] = s;
        st[tid] = bnb[tid] - m * s;
    }
    __syncthreads();
    if (tid < NC) {
        float acc = bias_in[tid];
        #pragma unroll 4
        for (int f = 0; f < HH; f++) {
            float m = Msrc[f*NC + tid];
            Wdst[f*NC + tid] = ss[f] * m;
            acc = fmaf(st[f], m, acc);
        }
        bias_out[tid] = acc;
    }
}

// ---------------- single-pass bucketed edge build ----------------
__global__ void scatter_kernel(const int* __restrict__ rows, const int* __restrict__ cols,
                               const float* __restrict__ vals)
{
    int gid = blockIdx.x * 256 + threadIdx.x;
    if (gid >= BB*EE) return;
    int b = gid >> 18;                 // E = 2^18
    int idx = b*NN + rows[gid];
    int pos = atomicAdd(&g_cnt[idx], 1);
    if (pos < CAP) {
        uint vh = (uint)__half_as_ushort(__float2half_rn(vals[gid]));
        g_bkt[(size_t)idx*CAP + pos] = (vh << 16) | (uint)cols[gid];
    }
}

// ---------------- SpMM aggregate (fp16 gather) + norm + mask + relu + bnc stats --------
// grid = TOT/8, block = 128 (4 warps). Warp w handles rows {blk*8+w, blk*8+4+w}.
// Lane j owns features [4j, 4j+3]; per edge a warp gathers one hc row as 32x uint2.
__global__ void agg_kernel(const int* __restrict__ nn)
{
    __shared__ float s_ls[HH], s_lq[HH];
    int tid = threadIdx.x, w = tid >> 5, lane = tid & 31;
    for (int i = tid; i < HH; i += 128) { s_ls[i] = 0.f; s_lq[i] = 0.f; }
    __syncthreads();

    float ls[4] = {0,0,0,0}, lq[4] = {0,0,0,0};
    #pragma unroll 1
    for (int ri = 0; ri < 2; ri++) {
        int idx = blockIdx.x * 8 + ri*4 + w;
        int b = idx >> 13, r = idx & (NN - 1);
        int len = min(g_cnt[idx], CAP);
        const uint2* hcb = (const uint2*)g_hcp + (size_t)b*NN*32;
        const uint*  ep  = g_bkt + (size_t)idx*CAP;

        float a0=0.f, a1=0.f, a2=0.f, a3=0.f, ds=0.f;
        for (int e0 = 0; e0 < len; e0 += 32) {
            uint my = (e0 + lane < len) ? ep[e0 + lane] : 0u;
            int m = min(32, len - e0);
            int t = 0;
            for (; t + 2 <= m; t += 2) {
                uint ea = __shfl_sync(0xffffffffu, my, t);
                uint eb = __shfl_sync(0xffffffffu, my, t+1);
                float va = __half2float(__ushort_as_half((unsigned short)(ea >> 16)));
                float vb = __half2float(__ushort_as_half((unsigned short)(eb >> 16)));
                uint2 ha = hcb[(size_t)(ea & 0xFFFFu)*32 + lane];
                uint2 hb = hcb[(size_t)(eb & 0xFFFFu)*32 + lane];
                float2 fa0 = h2f(ha.x), fa1 = h2f(ha.y);
                float2 fb0 = h2f(hb.x), fb1 = h2f(hb.y);
                a0 = fmaf(va, fa0.x, a0);  a1 = fmaf(va, fa0.y, a1);
                a2 = fmaf(va, fa1.x, a2);  a3 = fmaf(va, fa1.y, a3);
                a0 = fmaf(vb, fb0.x, a0);  a1 = fmaf(vb, fb0.y, a1);
                a2 = fmaf(vb, fb1.x, a2);  a3 = fmaf(vb, fb1.y, a3);
                ds += va + vb;
            }
            if (t < m) {
                uint ea = __shfl_sync(0xffffffffu, my, t);
                float va = __half2float(__ushort_as_half((unsigned short)(ea >> 16)));
                uint2 ha = hcb[(size_t)(ea & 0xFFFFu)*32 + lane];
                float2 fa0 = h2f(ha.x), fa1 = h2f(ha.y);
                a0 = fmaf(va, fa0.x, a0);  a1 = fmaf(va, fa0.y, a1);
                a2 = fmaf(va, fa1.x, a2);  a3 = fmaf(va, fa1.y, a3);
                ds += va;
            }
        }
        float inv = 1.f / fmaxf(ds, 1.f);
        bool dead = (r >= nn[b]);
        float4 o;
        o.x = dead ? 0.f : fmaxf(a0*inv, 0.f);
        o.y = dead ? 0.f : fmaxf(a1*inv, 0.f);
        o.z = dead ? 0.f : fmaxf(a2*inv, 0.f);
        o.w = dead ? 0.f : fmaxf(a3*inv, 0.f);
        *(float4*)&g_h1[(size_t)idx*HH + lane*4] = o;
        ls[0]+=o.x; lq[0]+=o.x*o.x;  ls[1]+=o.y; lq[1]+=o.y*o.y;
        ls[2]+=o.z; lq[2]+=o.z*o.z;  ls[3]+=o.w; lq[3]+=o.w*o.w;
    }
    #pragma unroll
    for (int q = 0; q < 4; q++) {
        atomicAdd(&s_ls[lane*4+q], ls[q]);
        atomicAdd(&s_lq[lane*4+q], lq[q]);
    }
    __syncthreads();
    for (int i = tid; i < HH; i += 128) {
        atomicAdd(&g_stat[1*2*HH + i],      s_ls[i]);
        atomicAdd(&g_stat[1*2*HH + HH + i], s_lq[i]);
    }
}

// ---------------- tiled fp32 GEMM with packed f32x2 FMAs ----------------
// BM rows/block, 256 threads, micro-tile (BM/16) rows x (NC/16) cols per thread.
template<int BM, int K, int NC, bool RELU, int STAGE, bool OUT16>   // STAGE<0: no stats
__global__ __launch_bounds__(256)
void gemm_kernel(const float* __restrict__ A, const float* __restrict__ Wm,
                 const float* __restrict__ bias, void* __restrict__ Cv)
{
    extern __shared__ float sm[];
    constexpr int AST = K + 4;
    float* As = sm;                            // [BM][AST]
    float* Ws = sm + BM*AST;                   // [K][NC]
    int tid = threadIdx.x;
    size_t row0 = (size_t)blockIdx.x * BM;

    const float4* Ag = (const float4*)(A + row0*K);
    #pragma unroll 4
    for (int i = tid; i < BM*K/4; i += 256) {
        float4 v = Ag[i];
        int r = (i*4)/K, k = (i*4)%K;
        *(float4*)&As[r*AST + k] = v;
    }
    #pragma unroll 4
    for (int i = tid; i < K*NC/4; i += 256) ((float4*)Ws)[i] = ((const float4*)Wm)[i];
    __syncthreads();

    constexpr int RPT = BM/16;    // rows per thread
    constexpr int CPT = NC/16;    // cols per thread
    constexpr int CP2 = CPT/2;
    int cg = tid & 15, rg = tid >> 4;
    const float* Arow = As + rg*RPT*AST;
    const float* Wcol = Ws + cg*CPT;

    ull acc[RPT][CP2];
    #pragma unroll
    for (int i = 0; i < RPT; i++)
        #pragma unroll
        for (int j = 0; j < CP2; j++) acc[i][j] = 0ull;

    #pragma unroll 2
    for (int k0 = 0; k0 < K; k0 += 4) {
        float4 a4[RPT];
        #pragma unroll
        for (int i = 0; i < RPT; i++) a4[i] = *(const float4*)&Arow[i*AST + k0];
        #pragma unroll
        for (int kk = 0; kk < 4; kk++) {
            ull w2[CP2];
            #pragma unroll
            for (int j = 0; j < CP2; j++)
                w2[j] = *(const ull*)&Wcol[(k0+kk)*NC + 2*j];
            #pragma unroll
            for (int i = 0; i < RPT; i++) {
                float av = (kk == 0) ? a4[i].x : (kk == 1) ? a4[i].y
                         : (kk == 2) ? a4[i].z : a4[i].w;
                ull a2 = dup_f32(av);
                #pragma unroll
                for (int j = 0; j < CP2; j++) fma2(acc[i][j], a2, w2[j]);
            }
        }
    }

    float ls[CPT], lq[CPT];
    #pragma unroll
    for (int j = 0; j < CP2; j++) {
        int c0 = cg*CPT + 2*j;
        float b0v = bias[c0], b1v = bias[c0+1];
        ls[2*j] = 0.f; lq[2*j] = 0.f; ls[2*j+1] = 0.f; lq[2*j+1] = 0.f;
        #pragma unroll
        for (int i = 0; i < RPT; i++) {
            float lo, hi;
            unpack2(lo, hi, acc[i][j]);
            float v0 = lo + b0v, v1 = hi + b1v;
            if (RELU) { v0 = fmaxf(v0, 0.f); v1 = fmaxf(v1, 0.f); }
            if (OUT16) {
                __half2 p = __float22half2_rn(make_float2(v0, v1));
                ((uint*)Cv)[(row0 + rg*RPT + i)*(NC/2) + c0/2] = *(uint*)&p;
            } else {
                *(float2*)&((float*)Cv)[(row0 + rg*RPT + i)*NC + c0] = make_float2(v0, v1);
            }
            if (STAGE >= 0) { ls[2*j] += v0; lq[2*j] += v0*v0; ls[2*j+1] += v1; lq[2*j+1] += v1*v1; }
        }
    }

    if (STAGE >= 0) {
        __syncthreads();
        float* ps = sm;
        float* pq = sm + 16*NC;
        #pragma unroll
        for (int j = 0; j < CPT; j++) {
            ps[rg*NC + cg*CPT + j] = ls[j];
            pq[rg*NC + cg*CPT + j] = lq[j];
        }
        __syncthreads();
        if (tid < NC) {
            float s = 0.f, q = 0.f;
            #pragma unroll
            for (int g = 0; g < 16; g++) { s += ps[g*NC + tid]; q += pq[g*NC + tid]; }
            atomicAdd(&g_stat[STAGE*2*HH + tid],      s);
            atomicAdd(&g_stat[STAGE*2*HH + HH + tid], q);
        }
    }
}

// ---------------- host launcher ----------------
extern "C" void kernel_launch(void* const* d_in, const int* in_sizes, int n_in,
                              void* d_out, int out_size)
{
    const float* x    = (const float*)d_in[0];
    const int*   erow = (const int*)  d_in[1];
    const int*   ecol = (const int*)  d_in[2];
    const float* evl  = (const float*)d_in[3];
    const int*   nn   = (const int*)  d_in[4];
    const float* W0   = (const float*)d_in[5];
    const float* b0   = (const float*)d_in[6];
    const float* W02  = (const float*)d_in[7];
    const float* b02  = (const float*)d_in[8];
    const float* Wc   = (const float*)d_in[9];
    const float* bc   = (const float*)d_in[10];
    const float* W1   = (const float*)d_in[11];
    const float* b1   = (const float*)d_in[12];
    const float* W2   = (const float*)d_in[13];
    const float* b2   = (const float*)d_in[14];
    const float* bn0w = (const float*)d_in[15];
    const float* bn0b = (const float*)d_in[16];
    const float* bncw = (const float*)d_in[17];
    const float* bncb = (const float*)d_in[18];
    const float* bn1w = (const float*)d_in[19];
    const float* bn1b = (const float*)d_in[20];
    float* out = (float*)d_out;

    float *p_h0, *p_h1, *p_h2, *p_M, *p_Wa, *p_ba, *p_Wb, *p_bb, *p_Wo, *p_bo;
    uint  *p_hcp;
    cudaGetSymbolAddress((void**)&p_h0,  g_h0);
    cudaGetSymbolAddress((void**)&p_hcp, g_hcp);
    cudaGetSymbolAddress((void**)&p_h1,  g_h1);
    cudaGetSymbolAddress((void**)&p_h2,  g_h2);
    cudaGetSymbolAddress((void**)&p_M,   g_M);
    cudaGetSymbolAddress((void**)&p_Wa,  g_Wa);
    cudaGetSymbolAddress((void**)&p_ba,  g_ba);
    cudaGetSymbolAddress((void**)&p_Wb,  g_Wb);
    cudaGetSymbolAddress((void**)&p_bb,  g_bb);
    cudaGetSymbolAddress((void**)&p_Wo,  g_Wo);
    cudaGetSymbolAddress((void**)&p_bo,  g_bo);

    const size_t sm1 = (128*(FIN+4) + (size_t)FIN*HH) * sizeof(float);  // BM=128,K=64
    const size_t sm2 = (64*(HH+4)   + (size_t)HH*HH)  * sizeof(float);  // BM=64, K=128
    const size_t sm3 = (128*(HH+4)  + (size_t)HH*FOUT)* sizeof(float);  // BM=128,K=128,NC=32
    cudaFuncSetAttribute(gemm_kernel<128,FIN,HH,true,0,false>,    cudaFuncAttributeMaxDynamicSharedMemorySize, (int)sm1);
    cudaFuncSetAttribute(gemm_kernel<64,HH,HH,false,-1,true>,     cudaFuncAttributeMaxDynamicSharedMemorySize, (int)sm2);
    cudaFuncSetAttribute(gemm_kernel<64,HH,HH,true,2,false>,      cudaFuncAttributeMaxDynamicSharedMemorySize, (int)sm2);
    cudaFuncSetAttribute(gemm_kernel<128,HH,FOUT,false,-1,false>, cudaFuncAttributeMaxDynamicSharedMemorySize, (int)sm3);

    // init + single-pass bucketed edge build
    init_kernel<<<TOT/256 + 1, 256>>>(b02, Wc, bc);
    scatter_kernel<<<(BB*EE)/256, 256>>>(erow, ecol, evl);

    // layer 0: h0 = relu(x@W0 + b0), bn0 stats fused
    gemm_kernel<128,FIN,HH,true,0,false><<<TOT/128, 256, sm1>>>(x, W0, b0, p_h0);

    // fold bn0 into (W02@Wc)
    mm128_kernel<<<HH, HH>>>(W02, Wc);
    fold_kernel<<<1, 128>>>(bn0w, bn0b, 0, p_M, p_Wa, p_ba, p_ba, HH);

    // hc = h0 @ Wa + ba   (fp16x2 output)
    gemm_kernel<64,HH,HH,false,-1,true><<<TOT/64, 256, sm2>>>(p_h0, p_Wa, p_ba, p_hcp);

    // SGC aggregate (+mask, relu, bnc stats)
    agg_kernel<<<TOT/8, 128>>>(nn);

    // fold bnc into W1
    fold_kernel<<<1, 128>>>(bncw, bncb, 1, W1, p_Wb, b1, p_bb, HH);

    // h2 = relu(h1 @ Wb + bb), bn1 stats fused
    gemm_kernel<64,HH,HH,true,2,false><<<TOT/64, 256, sm2>>>(p_h1, p_Wb, p_bb, p_h2);

    // fold bn1 into W2
    fold_kernel<<<1, 128>>>(bn1w, bn1b, 2, W2, p_Wo, b2, p_bo, FOUT);

    // out = h2 @ Wo + bo
    gemm_kernel<128,HH,FOUT,false,-1,false><<<TOT/128, 256, sm3>>>(p_h2, p_Wo, p_bo, out);
}

// round 9
// speedup vs baseline: 1.2152x; 1.2152x over previous
#include <cuda_runtime.h>
#include <cuda_fp16.h>
#include <cstdint>

#define BB   8
#define NN   8192
#define EE   262144
#define FIN  64
#define HH   128
#define FOUT 32
#define TOT  (BB*NN)   // 65536 rows total

typedef unsigned long long ull;
typedef unsigned int uint;

// ---------------- device scratch (no allocations allowed) ----------------
__device__ float g_h0[(size_t)TOT*HH];
__device__ uint  g_hcp[(size_t)TOT*(HH/2)];   // hc as fp16x2 pairs
__device__ float g_h1[(size_t)TOT*HH];
__device__ float g_h2[(size_t)TOT*HH];
__device__ int   g_cnt[TOT];
__device__ int   g_cursor[TOT];
__device__ int   g_rowstart[TOT];
__device__ uint  g_epk[(size_t)BB*EE];        // packed edge: [fp16 val | 16-bit col]
__device__ float g_stat[6*HH];                // [stage][sum|sumsq][H], stages 0..2
__device__ float g_Wa[HH*HH];
__device__ float g_ba[HH];
__device__ float g_Wb[HH*HH];
__device__ float g_bb[HH];
__device__ float g_Wo[HH*FOUT];
__device__ float g_bo[FOUT];

__device__ __forceinline__ ull dup_f32(float a) {
    ull d; asm("mov.b64 %0, {%1, %1};" : "=l"(d) : "f"(a)); return d;
}
__device__ __forceinline__ void fma2(ull& acc, ull a, ull b) {
    asm("fma.rn.f32x2 %0, %1, %2, %0;" : "+l"(acc) : "l"(a), "l"(b));
}
__device__ __forceinline__ void unpack2(float& lo, float& hi, ull v) {
    asm("mov.b64 {%0, %1}, %2;" : "=f"(lo), "=f"(hi) : "l"(v));
}
__device__ __forceinline__ float2 h2f(uint p) {
    return __half22float2(*reinterpret_cast<__half2*>(&p));
}
// BN affine coefficients from accumulated stats
__device__ __forceinline__ void bn_st(int stage, int f, const float* bnw, const float* bnb,
                                      float& s, float& t) {
    float cnt = (float)TOT;
    float sum = g_stat[stage*2*HH + f];
    float sq  = g_stat[stage*2*HH + HH + f];
    float m = sum / cnt;
    float v = sq / cnt - m*m;
    float inv = rsqrtf(v + 1e-5f);
    s = bnw[f] * inv;
    t = bnb[f] - m * s;
}

// ---------------- init: zero accumulators, seed fused biases ----------------
__global__ void init_kernel(const float* __restrict__ b02, const float* __restrict__ Wc,
                            const float* __restrict__ bc,  const float* __restrict__ b1,
                            const float* __restrict__ b2)
{
    int gid = blockIdx.x * 256 + threadIdx.x;
    if (gid < TOT) g_cnt[gid] = 0;
    if (gid < 6*HH) g_stat[gid] = 0.f;
    if (blockIdx.x == gridDim.x - 1) {
        int k = threadIdx.x;
        if (k < HH) {
            float s = bc[k];
            #pragma unroll 8
            for (int f = 0; f < HH; f++) s += b02[f] * Wc[f*HH + k];
            g_ba[k] = s;          // (b02 @ Wc + bc); fold0 adds t0 @ (W02@Wc)
            g_bb[k] = b1[k];      // fold1 adds t1 @ W1
        }
        if (k < FOUT) g_bo[k] = b2[k];   // fold2 adds t2 @ W2
    }
}

// ---------------- fused BN0-fold + W02@Wc: Wa[f,:] = s0[f]*(W02[f,:]@Wc) ------------
// grid = 128 (one block per f-row), block = 128, Wc staged in smem.
__global__ void fold0_kernel(const float* __restrict__ bnw, const float* __restrict__ bnb,
                             const float* __restrict__ W02, const float* __restrict__ Wc)
{
    extern __shared__ float sh[];               // [HH*HH] Wc + [HH] w02 row + 2
    float* Wcs = sh;
    float* row = sh + HH*HH;
    float* stp = sh + HH*HH + HH;
    int f = blockIdx.x, k = threadIdx.x;

    #pragma unroll 8
    for (int i = k; i < HH*HH/4; i += HH) ((float4*)Wcs)[i] = ((const float4*)Wc)[i];
    row[k] = W02[f*HH + k];
    if (k == 0) { float s, t; bn_st(0, f, bnw, bnb, s, t); stp[0] = s; stp[1] = t; }
    __syncthreads();

    float m = 0.f;
    #pragma unroll 8
    for (int j = 0; j < HH; j++) m = fmaf(row[j], Wcs[j*HH + k], m);
    g_Wa[f*HH + k] = stp[0] * m;
    atomicAdd(&g_ba[k], stp[1] * m);
}

// ---------------- parallel BN fold: Wdst[f,k] = s[f]*Msrc[f,k], bias += t[f]*Msrc[f,k]
// grid = 128 (one block per f), block = 128 (k, guarded by NC). bias pre-seeded.
template<int NC>
__global__ void fold_kernel(const float* __restrict__ bnw, const float* __restrict__ bnb,
                            int stage, const float* __restrict__ Msrc,
                            float* __restrict__ Wdst, float* __restrict__ bias)
{
    __shared__ float stp[2];
    int f = blockIdx.x, k = threadIdx.x;
    if (k == 0) { float s, t; bn_st(stage, f, bnw, bnb, s, t); stp[0] = s; stp[1] = t; }
    __syncthreads();
    if (k < NC) {
        float m = Msrc[f*NC + k];
        Wdst[f*NC + k] = stp[0] * m;
        atomicAdd(&bias[k], stp[1] * m);
    }
}

// ---------------- CSR build ----------------
__global__ void count_kernel(const int* __restrict__ rows)
{
    int gid = blockIdx.x * 256 + threadIdx.x;
    if (gid >= BB*EE) return;
    int b = gid >> 18;                 // E = 2^18
    atomicAdd(&g_cnt[b*NN + rows[gid]], 1);
}

__global__ void scan_kernel()          // grid=8 (batches), block=1024
{
    int b = blockIdx.x, t = threadIdx.x;
    int base = b*NN + t*8;
    int v[8], pre[8], tot = 0;
    #pragma unroll
    for (int i = 0; i < 8; i++) { v[i] = g_cnt[base+i]; pre[i] = tot; tot += v[i]; }
    int lane = t & 31, w = t >> 5;
    int x = tot;
    #pragma unroll
    for (int o = 1; o < 32; o <<= 1) { int y = __shfl_up_sync(0xffffffffu, x, o); if (lane >= o) x += y; }
    __shared__ int wsum[32];
    if (lane == 31) wsum[w] = x;
    __syncthreads();
    if (w == 0) {
        int y = wsum[lane];
        #pragma unroll
        for (int o = 1; o < 32; o <<= 1) { int z = __shfl_up_sync(0xffffffffu, y, o); if (lane >= o) y += z; }
        wsum[lane] = y;
    }
    __syncthreads();
    int ex = x - tot + (w > 0 ? wsum[w-1] : 0);
    #pragma unroll
    for (int i = 0; i < 8; i++) {
        int st = ex + pre[i];
        g_rowstart[base+i] = st;
        g_cursor[base+i]  = st;
    }
}

__global__ void scatter_kernel(const int* __restrict__ rows, const int* __restrict__ cols,
                               const float* __restrict__ vals)
{
    int gid = blockIdx.x * 256 + threadIdx.x;
    if (gid >= BB*EE) return;
    int b = gid >> 18;
    int r = rows[gid];
    int pos = atomicAdd(&g_cursor[b*NN + r], 1);
    uint vh = (uint)__half_as_ushort(__float2half_rn(vals[gid]));
    g_epk[(size_t)b*EE + pos] = (vh << 16) | (uint)cols[gid];
}

// ---------------- SpMM aggregate (fp16 gather) + norm + mask + relu + bnc stats --------
__global__ void agg_kernel(const int* __restrict__ nn)
{
    __shared__ float s_ls[HH], s_lq[HH];
    int tid = threadIdx.x, w = tid >> 5, lane = tid & 31;
    for (int i = tid; i < HH; i += 128) { s_ls[i] = 0.f; s_lq[i] = 0.f; }
    __syncthreads();

    float ls[4] = {0,0,0,0}, lq[4] = {0,0,0,0};
    #pragma unroll 1
    for (int ri = 0; ri < 2; ri++) {
        int idx = blockIdx.x * 8 + ri*4 + w;
        int b = idx >> 13, r = idx & (NN - 1);
        int start = g_rowstart[idx], len = g_cnt[idx];
        const uint2* hcb = (const uint2*)g_hcp + (size_t)b*NN*32;
        const uint*  ep  = g_epk + (size_t)b*EE + start;

        float a0=0.f, a1=0.f, a2=0.f, a3=0.f, ds=0.f;
        for (int e0 = 0; e0 < len; e0 += 32) {
            uint my = (e0 + lane < len) ? ep[e0 + lane] : 0u;
            int m = min(32, len - e0);
            int t = 0;
            for (; t + 2 <= m; t += 2) {
                uint ea = __shfl_sync(0xffffffffu, my, t);
                uint eb = __shfl_sync(0xffffffffu, my, t+1);
                float va = __half2float(__ushort_as_half((unsigned short)(ea >> 16)));
                float vb = __half2float(__ushort_as_half((unsigned short)(eb >> 16)));
                uint2 ha = hcb[(size_t)(ea & 0xFFFFu)*32 + lane];
                uint2 hb = hcb[(size_t)(eb & 0xFFFFu)*32 + lane];
                float2 fa0 = h2f(ha.x), fa1 = h2f(ha.y);
                float2 fb0 = h2f(hb.x), fb1 = h2f(hb.y);
                a0 = fmaf(va, fa0.x, a0);  a1 = fmaf(va, fa0.y, a1);
                a2 = fmaf(va, fa1.x, a2);  a3 = fmaf(va, fa1.y, a3);
                a0 = fmaf(vb, fb0.x, a0);  a1 = fmaf(vb, fb0.y, a1);
                a2 = fmaf(vb, fb1.x, a2);  a3 = fmaf(vb, fb1.y, a3);
                ds += va + vb;
            }
            if (t < m) {
                uint ea = __shfl_sync(0xffffffffu, my, t);
                float va = __half2float(__ushort_as_half((unsigned short)(ea >> 16)));
                uint2 ha = hcb[(size_t)(ea & 0xFFFFu)*32 + lane];
                float2 fa0 = h2f(ha.x), fa1 = h2f(ha.y);
                a0 = fmaf(va, fa0.x, a0);  a1 = fmaf(va, fa0.y, a1);
                a2 = fmaf(va, fa1.x, a2);  a3 = fmaf(va, fa1.y, a3);
                ds += va;
            }
        }
        float inv = 1.f / fmaxf(ds, 1.f);
        bool dead = (r >= nn[b]);
        float4 o;
        o.x = dead ? 0.f : fmaxf(a0*inv, 0.f);
        o.y = dead ? 0.f : fmaxf(a1*inv, 0.f);
        o.z = dead ? 0.f : fmaxf(a2*inv, 0.f);
        o.w = dead ? 0.f : fmaxf(a3*inv, 0.f);
        *(float4*)&g_h1[(size_t)idx*HH + lane*4] = o;
        ls[0]+=o.x; lq[0]+=o.x*o.x;  ls[1]+=o.y; lq[1]+=o.y*o.y;
        ls[2]+=o.z; lq[2]+=o.z*o.z;  ls[3]+=o.w; lq[3]+=o.w*o.w;
    }
    #pragma unroll
    for (int q = 0; q < 4; q++) {
        atomicAdd(&s_ls[lane*4+q], ls[q]);
        atomicAdd(&s_lq[lane*4+q], lq[q]);
    }
    __syncthreads();
    for (int i = tid; i < HH; i += 128) {
        atomicAdd(&g_stat[1*2*HH + i],      s_ls[i]);
        atomicAdd(&g_stat[1*2*HH + HH + i], s_lq[i]);
    }
}

// ---------------- tiled fp32 GEMM with packed f32x2 FMAs ----------------
// BM=128 rows/block, 256 threads, micro-tile 8 rows x (NC/16) cols per thread.
template<int K, int NC, bool RELU, int STAGE, bool OUT16>   // STAGE<0: no stats
__global__ __launch_bounds__(256)
void gemm_kernel(const float* __restrict__ A, const float* __restrict__ Wm,
                 const float* __restrict__ bias, void* __restrict__ Cv)
{
    extern __shared__ float sm[];
    constexpr int AST = K + 4;
    float* As = sm;                            // [128][AST]
    float* Ws = sm + 128*AST;                  // [K][NC]
    int tid = threadIdx.x;
    size_t row0 = (size_t)blockIdx.x * 128;

    const float4* Ag = (const float4*)(A + row0*K);
    #pragma unroll 4
    for (int i = tid; i < 128*K/4; i += 256) {
        float4 v = Ag[i];
        int r = (i*4)/K, k = (i*4)%K;
        *(float4*)&As[r*AST + k] = v;
    }
    #pragma unroll 4
    for (int i = tid; i < K*NC/4; i += 256) ((float4*)Ws)[i] = ((const float4*)Wm)[i];
    __syncthreads();

    constexpr int CPT = NC/16;    // 8 (NC=128) or 2 (NC=32)
    constexpr int CP2 = CPT/2;
    int cg = tid & 15, rg = tid >> 4;
    const float* Arow = As + rg*8*AST;
    const float* Wcol = Ws + cg*CPT;

    ull acc[8][CP2];
    #pragma unroll
    for (int i = 0; i < 8; i++)
        #pragma unroll
        for (int j = 0; j < CP2; j++) acc[i][j] = 0ull;

    #pragma unroll 2
    for (int k0 = 0; k0 < K; k0 += 4) {
        float4 a4[8];
        #pragma unroll
        for (int i = 0; i < 8; i++) a4[i] = *(const float4*)&Arow[i*AST + k0];
        #pragma unroll
        for (int kk = 0; kk < 4; kk++) {
            ull w2[CP2];
            #pragma unroll
            for (int j = 0; j < CP2; j++)
                w2[j] = *(const ull*)&Wcol[(k0+kk)*NC + 2*j];
            #pragma unroll
            for (int i = 0; i < 8; i++) {
                float av = (kk == 0) ? a4[i].x : (kk == 1) ? a4[i].y
                         : (kk == 2) ? a4[i].z : a4[i].w;
                ull a2 = dup_f32(av);
                #pragma unroll
                for (int j = 0; j < CP2; j++) fma2(acc[i][j], a2, w2[j]);
            }
        }
    }

    float ls[CPT], lq[CPT];
    #pragma unroll
    for (int j = 0; j < CP2; j++) {
        int c0 = cg*CPT + 2*j;
        float b0v = bias[c0], b1v = bias[c0+1];
        ls[2*j] = 0.f; lq[2*j] = 0.f; ls[2*j+1] = 0.f; lq[2*j+1] = 0.f;
        #pragma unroll
        for (int i = 0; i < 8; i++) {
            float lo, hi;
            unpack2(lo, hi, acc[i][j]);
            float v0 = lo + b0v, v1 = hi + b1v;
            if (RELU) { v0 = fmaxf(v0, 0.f); v1 = fmaxf(v1, 0.f); }
            if (OUT16) {
                __half2 p = __float22half2_rn(make_float2(v0, v1));
                ((uint*)Cv)[(row0 + rg*8 + i)*(NC/2) + c0/2] = *(uint*)&p;
            } else {
                *(float2*)&((float*)Cv)[(row0 + rg*8 + i)*NC + c0] = make_float2(v0, v1);
            }
            if (STAGE >= 0) { ls[2*j] += v0; lq[2*j] += v0*v0; ls[2*j+1] += v1; lq[2*j+1] += v1*v1; }
        }
    }

    if (STAGE >= 0) {
        __syncthreads();
        float* ps = sm;
        float* pq = sm + 16*NC;
        #pragma unroll
        for (int j = 0; j < CPT; j++) {
            ps[rg*NC + cg*CPT + j] = ls[j];
            pq[rg*NC + cg*CPT + j] = lq[j];
        }
        __syncthreads();
        if (tid < NC) {
            float s = 0.f, q = 0.f;
            #pragma unroll
            for (int g = 0; g < 16; g++) { s += ps[g*NC + tid]; q += pq[g*NC + tid]; }
            atomicAdd(&g_stat[STAGE*2*HH + tid],      s);
            atomicAdd(&g_stat[STAGE*2*HH + HH + tid], q);
        }
    }
}

// ---------------- host launcher ----------------
extern "C" void kernel_launch(void* const* d_in, const int* in_sizes, int n_in,
                              void* d_out, int out_size)
{
    const float* x    = (const float*)d_in[0];
    const int*   erow = (const int*)  d_in[1];
    const int*   ecol = (const int*)  d_in[2];
    const float* evl  = (const float*)d_in[3];
    const int*   nn   = (const int*)  d_in[4];
    const float* W0   = (const float*)d_in[5];
    const float* b0   = (const float*)d_in[6];
    const float* W02  = (const float*)d_in[7];
    const float* b02  = (const float*)d_in[8];
    const float* Wc   = (const float*)d_in[9];
    const float* bc   = (const float*)d_in[10];
    const float* W1   = (const float*)d_in[11];
    const float* b1   = (const float*)d_in[12];
    const float* W2   = (const float*)d_in[13];
    const float* b2   = (const float*)d_in[14];
    const float* bn0w = (const float*)d_in[15];
    const float* bn0b = (const float*)d_in[16];
    const float* bncw = (const float*)d_in[17];
    const float* bncb = (const float*)d_in[18];
    const float* bn1w = (const float*)d_in[19];
    const float* bn1b = (const float*)d_in[20];
    float* out = (float*)d_out;

    float *p_h0, *p_h1, *p_h2, *p_Wa, *p_ba, *p_Wb, *p_bb, *p_Wo, *p_bo;
    uint  *p_hcp;
    cudaGetSymbolAddress((void**)&p_h0,  g_h0);
    cudaGetSymbolAddress((void**)&p_hcp, g_hcp);
    cudaGetSymbolAddress((void**)&p_h1,  g_h1);
    cudaGetSymbolAddress((void**)&p_h2,  g_h2);
    cudaGetSymbolAddress((void**)&p_Wa,  g_Wa);
    cudaGetSymbolAddress((void**)&p_ba,  g_ba);
    cudaGetSymbolAddress((void**)&p_Wb,  g_Wb);
    cudaGetSymbolAddress((void**)&p_bb,  g_bb);
    cudaGetSymbolAddress((void**)&p_Wo,  g_Wo);
    cudaGetSymbolAddress((void**)&p_bo,  g_bo);

    const size_t sm1 = (128*(FIN+4) + (size_t)FIN*HH) * sizeof(float);
    const size_t sm2 = (128*(HH+4)  + (size_t)HH*HH)  * sizeof(float);
    const size_t sm3 = (128*(HH+4)  + (size_t)HH*FOUT)* sizeof(float);
    const size_t smf = ((size_t)HH*HH + HH + 2) * sizeof(float);
    cudaFuncSetAttribute(gemm_kernel<FIN,HH,true,0,false>,    cudaFuncAttributeMaxDynamicSharedMemorySize, (int)sm1);
    cudaFuncSetAttribute(gemm_kernel<HH,HH,false,-1,true>,    cudaFuncAttributeMaxDynamicSharedMemorySize, (int)sm2);
    cudaFuncSetAttribute(gemm_kernel<HH,HH,true,2,false>,     cudaFuncAttributeMaxDynamicSharedMemorySize, (int)sm2);
    cudaFuncSetAttribute(gemm_kernel<HH,FOUT,false,-1,false>, cudaFuncAttributeMaxDynamicSharedMemorySize, (int)sm3);
    cudaFuncSetAttribute(fold0_kernel, cudaFuncAttributeMaxDynamicSharedMemorySize, (int)smf);

    // init + CSR build
    init_kernel<<<TOT/256 + 1, 256>>>(b02, Wc, bc, b1, b2);
    count_kernel<<<(BB*EE)/256, 256>>>(erow);
    scan_kernel<<<BB, 1024>>>();
    scatter_kernel<<<(BB*EE)/256, 256>>>(erow, ecol, evl);

    // layer 0: h0 = relu(x@W0 + b0), bn0 stats fused
    gemm_kernel<FIN,HH,true,0,false><<<TOT/128, 256, sm1>>>(x, W0, b0, p_h0);

    // fused fold: Wa = diag(s0)*(W02@Wc), ba += t0@(W02@Wc)
    fold0_kernel<<<HH, HH, smf>>>(bn0w, bn0b, W02, Wc);

    // hc = h0 @ Wa + ba   (fp16x2 output)
    gemm_kernel<HH,HH,false,-1,true><<<TOT/128, 256, sm2>>>(p_h0, p_Wa, p_ba, p_hcp);

    // SGC aggregate (+mask, relu, bnc stats)
    agg_kernel<<<TOT/8, 128>>>(nn);

    // fold bnc into W1 (bb pre-seeded with b1)
    fold_kernel<HH><<<HH, 128>>>(bncw, bncb, 1, W1, p_Wb, p_bb);

    // h2 = relu(h1 @ Wb + bb), bn1 stats fused
    gemm_kernel<HH,HH,true,2,false><<<TOT/128, 256, sm2>>>(p_h1, p_Wb, p_bb, p_h2);

    // fold bn1 into W2 (bo pre-seeded with b2)
    fold_kernel<FOUT><<<HH, 128>>>(bn1w, bn1b, 2, W2, p_Wo, p_bo);

    // out = h2 @ Wo + bo
    gemm_kernel<HH,FOUT,false,-1,false><<<TOT/128, 256, sm3>>>(p_h2, p_Wo, p_bo, out);
}

// round 11
// speedup vs baseline: 1.2945x; 1.0653x over previous
#include <cuda_runtime.h>
#include <cuda_fp16.h>
#include <cstdint>

#define BB   8
#define NN   8192
#define EE   262144
#define FIN  64
#define HH   128
#define FOUT 32
#define TOT  (BB*NN)   // 65536 rows total

typedef unsigned long long ull;
typedef unsigned int uint;

// ---------------- device scratch (no allocations allowed) ----------------
__device__ float g_h0[(size_t)TOT*HH];
__device__ uint  g_hcp[(size_t)TOT*(HH/2)];   // hc as fp16x2 pairs
__device__ float g_h1[(size_t)TOT*HH];
__device__ float g_h2[(size_t)TOT*HH];
__device__ int   g_cnt[TOT];
__device__ int   g_cursor[TOT];
__device__ int   g_rowstart[TOT];
__device__ uint  g_epk[(size_t)BB*EE];        // packed edge: [fp16 val | 16-bit col]
__device__ float g_stat[6*HH];                // [stage][sum|sumsq][H], stages 0..2
__device__ float g_Wa[HH*HH];
__device__ float g_ba[HH];
__device__ float g_Wb[HH*HH];
__device__ float g_bb[HH];
__device__ float g_Wo[HH*FOUT];
__device__ float g_bo[FOUT];

// ---------------- side stream for fork-join overlap (created pre-main) -----------
struct SideCtx {
    cudaStream_t s = 0;
    cudaEvent_t  eFork = 0, eJoin = 0;
    bool ok = false;
    SideCtx() {
        ok = (cudaStreamCreateWithFlags(&s, cudaStreamNonBlocking) == cudaSuccess) &&
             (cudaEventCreateWithFlags(&eFork, cudaEventDisableTiming) == cudaSuccess) &&
             (cudaEventCreateWithFlags(&eJoin, cudaEventDisableTiming) == cudaSuccess);
    }
};
static SideCtx g_side;

__device__ __forceinline__ ull dup_f32(float a) {
    ull d; asm("mov.b64 %0, {%1, %1};" : "=l"(d) : "f"(a)); return d;
}
__device__ __forceinline__ void fma2(ull& acc, ull a, ull b) {
    asm("fma.rn.f32x2 %0, %1, %2, %0;" : "+l"(acc) : "l"(a), "l"(b));
}
__device__ __forceinline__ void unpack2(float& lo, float& hi, ull v) {
    asm("mov.b64 {%0, %1}, %2;" : "=f"(lo), "=f"(hi) : "l"(v));
}
__device__ __forceinline__ float2 h2f(uint p) {
    return __half22float2(*reinterpret_cast<__half2*>(&p));
}
// BN affine coefficients from accumulated stats
__device__ __forceinline__ void bn_st(int stage, int f, const float* bnw, const float* bnb,
                                      float& s, float& t) {
    float cnt = (float)TOT;
    float sum = g_stat[stage*2*HH + f];
    float sq  = g_stat[stage*2*HH + HH + f];
    float m = sum / cnt;
    float v = sq / cnt - m*m;
    float inv = rsqrtf(v + 1e-5f);
    s = bnw[f] * inv;
    t = bnb[f] - m * s;
}

// ---------------- init: zero accumulators, seed fused biases ----------------
__global__ void init_kernel(const float* __restrict__ b02, const float* __restrict__ Wc,
                            const float* __restrict__ bc,  const float* __restrict__ b1,
                            const float* __restrict__ b2)
{
    int gid = blockIdx.x * 256 + threadIdx.x;
    if (gid < TOT) g_cnt[gid] = 0;
    if (gid < 6*HH) g_stat[gid] = 0.f;
    if (blockIdx.x == gridDim.x - 1) {
        int k = threadIdx.x;
        if (k < HH) {
            float s = bc[k];
            #pragma unroll 8
            for (int f = 0; f < HH; f++) s += b02[f] * Wc[f*HH + k];
            g_ba[k] = s;          // (b02 @ Wc + bc); fold0 adds t0 @ (W02@Wc)
            g_bb[k] = b1[k];      // fold1 adds t1 @ W1
        }
        if (k < FOUT) g_bo[k] = b2[k];   // fold2 adds t2 @ W2
    }
}

// ---------------- fused BN0-fold + W02@Wc: Wa[f,:] = s0[f]*(W02[f,:]@Wc) ------------
__global__ void fold0_kernel(const float* __restrict__ bnw, const float* __restrict__ bnb,
                             const float* __restrict__ W02, const float* __restrict__ Wc)
{
    extern __shared__ float sh[];               // [HH*HH] Wc + [HH] w02 row + 2
    float* Wcs = sh;
    float* row = sh + HH*HH;
    float* stp = sh + HH*HH + HH;
    int f = blockIdx.x, k = threadIdx.x;

    #pragma unroll 8
    for (int i = k; i < HH*HH/4; i += HH) ((float4*)Wcs)[i] = ((const float4*)Wc)[i];
    row[k] = W02[f*HH + k];
    if (k == 0) { float s, t; bn_st(0, f, bnw, bnb, s, t); stp[0] = s; stp[1] = t; }
    __syncthreads();

    float m = 0.f;
    #pragma unroll 8
    for (int j = 0; j < HH; j++) m = fmaf(row[j], Wcs[j*HH + k], m);
    g_Wa[f*HH + k] = stp[0] * m;
    atomicAdd(&g_ba[k], stp[1] * m);
}

// ---------------- parallel BN fold ----------------
template<int NC>
__global__ void fold_kernel(const float* __restrict__ bnw, const float* __restrict__ bnb,
                            int stage, const float* __restrict__ Msrc,
                            float* __restrict__ Wdst, float* __restrict__ bias)
{
    __shared__ float stp[2];
    int f = blockIdx.x, k = threadIdx.x;
    if (k == 0) { float s, t; bn_st(stage, f, bnw, bnb, s, t); stp[0] = s; stp[1] = t; }
    __syncthreads();
    if (k < NC) {
        float m = Msrc[f*NC + k];
        Wdst[f*NC + k] = stp[0] * m;
        atomicAdd(&bias[k], stp[1] * m);
    }
}

// ---------------- CSR build (4 edges per thread for MLP) ----------------
__global__ void count_kernel(const int* __restrict__ rows)
{
    int gid = blockIdx.x * 256 + threadIdx.x;        // grid covers (BB*EE)/4
    int e0 = gid * 4;
    if (e0 >= BB*EE) return;
    int base = (e0 >> 18) * NN;                      // 4 edges never cross a batch
    int4 r = *(const int4*)(rows + e0);
    atomicAdd(&g_cnt[base + r.x], 1);
    atomicAdd(&g_cnt[base + r.y], 1);
    atomicAdd(&g_cnt[base + r.z], 1);
    atomicAdd(&g_cnt[base + r.w], 1);
}

__global__ void scan_kernel()          // grid=8 (batches), block=1024
{
    int b = blockIdx.x, t = threadIdx.x;
    int base = b*NN + t*8;
    int v[8], pre[8], tot = 0;
    #pragma unroll
    for (int i = 0; i < 8; i++) { v[i] = g_cnt[base+i]; pre[i] = tot; tot += v[i]; }
    int lane = t & 31, w = t >> 5;
    int x = tot;
    #pragma unroll
    for (int o = 1; o < 32; o <<= 1) { int y = __shfl_up_sync(0xffffffffu, x, o); if (lane >= o) x += y; }
    __shared__ int wsum[32];
    if (lane == 31) wsum[w] = x;
    __syncthreads();
    if (w == 0) {
        int y = wsum[lane];
        #pragma unroll
        for (int o = 1; o < 32; o <<= 1) { int z = __shfl_up_sync(0xffffffffu, y, o); if (lane >= o) y += z; }
        wsum[lane] = y;
    }
    __syncthreads();
    int ex = x - tot + (w > 0 ? wsum[w-1] : 0);
    #pragma unroll
    for (int i = 0; i < 8; i++) {
        int st = ex + pre[i];
        g_rowstart[base+i] = st;
        g_cursor[base+i]  = st;
    }
}

__global__ void scatter_kernel(const int* __restrict__ rows, const int* __restrict__ cols,
                               const float* __restrict__ vals)
{
    int gid = blockIdx.x * 256 + threadIdx.x;        // grid covers (BB*EE)/4
    int e0 = gid * 4;
    if (e0 >= BB*EE) return;
    int b = e0 >> 18;
    int base = b * NN;
    size_t ebase = (size_t)b * EE;
    int4   r = *(const int4*)(rows + e0);
    int4   c = *(const int4*)(cols + e0);
    float4 v = *(const float4*)(vals + e0);
    int p0 = atomicAdd(&g_cursor[base + r.x], 1);
    int p1 = atomicAdd(&g_cursor[base + r.y], 1);
    int p2 = atomicAdd(&g_cursor[base + r.z], 1);
    int p3 = atomicAdd(&g_cursor[base + r.w], 1);
    uint h0 = (uint)__half_as_ushort(__float2half_rn(v.x));
    uint h1 = (uint)__half_as_ushort(__float2half_rn(v.y));
    uint h2 = (uint)__half_as_ushort(__float2half_rn(v.z));
    uint h3 = (uint)__half_as_ushort(__float2half_rn(v.w));
    g_epk[ebase + p0] = (h0 << 16) | (uint)c.x;
    g_epk[ebase + p1] = (h1 << 16) | (uint)c.y;
    g_epk[ebase + p2] = (h2 << 16) | (uint)c.z;
    g_epk[ebase + p3] = (h3 << 16) | (uint)c.w;
}

// ---------------- SpMM aggregate (fp16 gather) + norm + mask + relu + bnc stats --------
__global__ void agg_kernel(const int* __restrict__ nn)
{
    __shared__ float s_ls[HH], s_lq[HH];
    int tid = threadIdx.x, w = tid >> 5, lane = tid & 31;
    for (int i = tid; i < HH; i += 128) { s_ls[i] = 0.f; s_lq[i] = 0.f; }
    __syncthreads();

    float ls[4] = {0,0,0,0}, lq[4] = {0,0,0,0};
    #pragma unroll 1
    for (int ri = 0; ri < 2; ri++) {
        int idx = blockIdx.x * 8 + ri*4 + w;
        int b = idx >> 13, r = idx & (NN - 1);
        int start = g_rowstart[idx], len = g_cnt[idx];
        const uint2* hcb = (const uint2*)g_hcp + (size_t)b*NN*32;
        const uint*  ep  = g_epk + (size_t)b*EE + start;

        float a0=0.f, a1=0.f, a2=0.f, a3=0.f, ds=0.f;
        for (int e0 = 0; e0 < len; e0 += 32) {
            uint my = (e0 + lane < len) ? ep[e0 + lane] : 0u;
            int m = min(32, len - e0);
            int t = 0;
            for (; t + 2 <= m; t += 2) {
                uint ea = __shfl_sync(0xffffffffu, my, t);
                uint eb = __shfl_sync(0xffffffffu, my, t+1);
                float va = __half2float(__ushort_as_half((unsigned short)(ea >> 16)));
                float vb = __half2float(__ushort_as_half((unsigned short)(eb >> 16)));
                uint2 ha = hcb[(size_t)(ea & 0xFFFFu)*32 + lane];
                uint2 hb = hcb[(size_t)(eb & 0xFFFFu)*32 + lane];
                float2 fa0 = h2f(ha.x), fa1 = h2f(ha.y);
                float2 fb0 = h2f(hb.x), fb1 = h2f(hb.y);
                a0 = fmaf(va, fa0.x, a0);  a1 = fmaf(va, fa0.y, a1);
                a2 = fmaf(va, fa1.x, a2);  a3 = fmaf(va, fa1.y, a3);
                a0 = fmaf(vb, fb0.x, a0);  a1 = fmaf(vb, fb0.y, a1);
                a2 = fmaf(vb, fb1.x, a2);  a3 = fmaf(vb, fb1.y, a3);
                ds += va + vb;
            }
            if (t < m) {
                uint ea = __shfl_sync(0xffffffffu, my, t);
                float va = __half2float(__ushort_as_half((unsigned short)(ea >> 16)));
                uint2 ha = hcb[(size_t)(ea & 0xFFFFu)*32 + lane];
                float2 fa0 = h2f(ha.x), fa1 = h2f(ha.y);
                a0 = fmaf(va, fa0.x, a0);  a1 = fmaf(va, fa0.y, a1);
                a2 = fmaf(va, fa1.x, a2);  a3 = fmaf(va, fa1.y, a3);
                ds += va;
            }
        }
        float inv = 1.f / fmaxf(ds, 1.f);
        bool dead = (r >= nn[b]);
        float4 o;
        o.x = dead ? 0.f : fmaxf(a0*inv, 0.f);
        o.y = dead ? 0.f : fmaxf(a1*inv, 0.f);
        o.z = dead ? 0.f : fmaxf(a2*inv, 0.f);
        o.w = dead ? 0.f : fmaxf(a3*inv, 0.f);
        *(float4*)&g_h1[(size_t)idx*HH + lane*4] = o;
        ls[0]+=o.x; lq[0]+=o.x*o.x;  ls[1]+=o.y; lq[1]+=o.y*o.y;
        ls[2]+=o.z; lq[2]+=o.z*o.z;  ls[3]+=o.w; lq[3]+=o.w*o.w;
    }
    #pragma unroll
    for (int q = 0; q < 4; q++) {
        atomicAdd(&s_ls[lane*4+q], ls[q]);
        atomicAdd(&s_lq[lane*4+q], lq[q]);
    }
    __syncthreads();
    for (int i = tid; i < HH; i += 128) {
        atomicAdd(&g_stat[1*2*HH + i],      s_ls[i]);
        atomicAdd(&g_stat[1*2*HH + HH + i], s_lq[i]);
    }
}

// ---------------- tiled fp32 GEMM with packed f32x2 FMAs ----------------
template<int K, int NC, bool RELU, int STAGE, bool OUT16>   // STAGE<0: no stats
__global__ __launch_bounds__(256)
void gemm_kernel(const float* __restrict__ A, const float* __restrict__ Wm,
                 const float* __restrict__ bias, void* __restrict__ Cv)
{
    extern __shared__ float sm[];
    constexpr int AST = K + 4;
    float* As = sm;                            // [128][AST]
    float* Ws = sm + 128*AST;                  // [K][NC]
    int tid = threadIdx.x;
    size_t row0 = (size_t)blockIdx.x * 128;

    const float4* Ag = (const float4*)(A + row0*K);
    #pragma unroll 4
    for (int i = tid; i < 128*K/4; i += 256) {
        float4 v = Ag[i];
        int r = (i*4)/K, k = (i*4)%K;
        *(float4*)&As[r*AST + k] = v;
    }
    #pragma unroll 4
    for (int i = tid; i < K*NC/4; i += 256) ((float4*)Ws)[i] = ((const float4*)Wm)[i];
    __syncthreads();

    constexpr int CPT = NC/16;    // 8 (NC=128) or 2 (NC=32)
    constexpr int CP2 = CPT/2;
    int cg = tid & 15, rg = tid >> 4;
    const float* Arow = As + rg*8*AST;
    const float* Wcol = Ws + cg*CPT;

    ull acc[8][CP2];
    #pragma unroll
    for (int i = 0; i < 8; i++)
        #pragma unroll
        for (int j = 0; j < CP2; j++) acc[i][j] = 0ull;

    #pragma unroll 2
    for (int k0 = 0; k0 < K; k0 += 4) {
        float4 a4[8];
        #pragma unroll
        for (int i = 0; i < 8; i++) a4[i] = *(const float4*)&Arow[i*AST + k0];
        #pragma unroll
        for (int kk = 0; kk < 4; kk++) {
            ull w2[CP2];
            #pragma unroll
            for (int j = 0; j < CP2; j++)
                w2[j] = *(const ull*)&Wcol[(k0+kk)*NC + 2*j];
            #pragma unroll
            for (int i = 0; i < 8; i++) {
                float av = (kk == 0) ? a4[i].x : (kk == 1) ? a4[i].y
                         : (kk == 2) ? a4[i].z : a4[i].w;
                ull a2 = dup_f32(av);
                #pragma unroll
                for (int j = 0; j < CP2; j++) fma2(acc[i][j], a2, w2[j]);
            }
        }
    }

    float ls[CPT], lq[CPT];
    #pragma unroll
    for (int j = 0; j < CP2; j++) {
        int c0 = cg*CPT + 2*j;
        float b0v = bias[c0], b1v = bias[c0+1];
        ls[2*j] = 0.f; lq[2*j] = 0.f; ls[2*j+1] = 0.f; lq[2*j+1] = 0.f;
        #pragma unroll
        for (int i = 0; i < 8; i++) {
            float lo, hi;
            unpack2(lo, hi, acc[i][j]);
            float v0 = lo + b0v, v1 = hi + b1v;
            if (RELU) { v0 = fmaxf(v0, 0.f); v1 = fmaxf(v1, 0.f); }
            if (OUT16) {
                __half2 p = __float22half2_rn(make_float2(v0, v1));
                ((uint*)Cv)[(row0 + rg*8 + i)*(NC/2) + c0/2] = *(uint*)&p;
            } else {
                *(float2*)&((float*)Cv)[(row0 + rg*8 + i)*NC + c0] = make_float2(v0, v1);
            }
            if (STAGE >= 0) { ls[2*j] += v0; lq[2*j] += v0*v0; ls[2*j+1] += v1; lq[2*j+1] += v1*v1; }
        }
    }

    if (STAGE >= 0) {
        __syncthreads();
        float* ps = sm;
        float* pq = sm + 16*NC;
        #pragma unroll
        for (int j = 0; j < CPT; j++) {
            ps[rg*NC + cg*CPT + j] = ls[j];
            pq[rg*NC + cg*CPT + j] = lq[j];
        }
        __syncthreads();
        if (tid < NC) {
            float s = 0.f, q = 0.f;
            #pragma unroll
            for (int g = 0; g < 16; g++) { s += ps[g*NC + tid]; q += pq[g*NC + tid]; }
            atomicAdd(&g_stat[STAGE*2*HH + tid],      s);
            atomicAdd(&g_stat[STAGE*2*HH + HH + tid], q);
        }
    }
}

// ---------------- host launcher ----------------
extern "C" void kernel_launch(void* const* d_in, const int* in_sizes, int n_in,
                              void* d_out, int out_size)
{
    const float* x    = (const float*)d_in[0];
    const int*   erow = (const int*)  d_in[1];
    const int*   ecol = (const int*)  d_in[2];
    const float* evl  = (const float*)d_in[3];
    const int*   nn   = (const int*)  d_in[4];
    const float* W0   = (const float*)d_in[5];
    const float* b0   = (const float*)d_in[6];
    const float* W02  = (const float*)d_in[7];
    const float* b02  = (const float*)d_in[8];
    const float* Wc   = (const float*)d_in[9];
    const float* bc   = (const float*)d_in[10];
    const float* W1   = (const float*)d_in[11];
    const float* b1   = (const float*)d_in[12];
    const float* W2   = (const float*)d_in[13];
    const float* b2   = (const float*)d_in[14];
    const float* bn0w = (const float*)d_in[15];
    const float* bn0b = (const float*)d_in[16];
    const float* bncw = (const float*)d_in[17];
    const float* bncb = (const float*)d_in[18];
    const float* bn1w = (const float*)d_in[19];
    const float* bn1b = (const float*)d_in[20];
    float* out = (float*)d_out;

    float *p_h0, *p_h1, *p_h2, *p_Wa, *p_ba, *p_Wb, *p_bb, *p_Wo, *p_bo;
    uint  *p_hcp;
    cudaGetSymbolAddress((void**)&p_h0,  g_h0);
    cudaGetSymbolAddress((void**)&p_hcp, g_hcp);
    cudaGetSymbolAddress((void**)&p_h1,  g_h1);
    cudaGetSymbolAddress((void**)&p_h2,  g_h2);
    cudaGetSymbolAddress((void**)&p_Wa,  g_Wa);
    cudaGetSymbolAddress((void**)&p_ba,  g_ba);
    cudaGetSymbolAddress((void**)&p_Wb,  g_Wb);
    cudaGetSymbolAddress((void**)&p_bb,  g_bb);
    cudaGetSymbolAddress((void**)&p_Wo,  g_Wo);
    cudaGetSymbolAddress((void**)&p_bo,  g_bo);

    const size_t sm1 = (128*(FIN+4) + (size_t)FIN*HH) * sizeof(float);
    const size_t sm2 = (128*(HH+4)  + (size_t)HH*HH)  * sizeof(float);
    const size_t sm3 = (128*(HH+4)  + (size_t)HH*FOUT)* sizeof(float);
    const size_t smf = ((size_t)HH*HH + HH + 2) * sizeof(float);
    cudaFuncSetAttribute(gemm_kernel<FIN,HH,true,0,false>,    cudaFuncAttributeMaxDynamicSharedMemorySize, (int)sm1);
    cudaFuncSetAttribute(gemm_kernel<HH,HH,false,-1,true>,    cudaFuncAttributeMaxDynamicSharedMemorySize, (int)sm2);
    cudaFuncSetAttribute(gemm_kernel<HH,HH,true,2,false>,     cudaFuncAttributeMaxDynamicSharedMemorySize, (int)sm2);
    cudaFuncSetAttribute(gemm_kernel<HH,FOUT,false,-1,false>, cudaFuncAttributeMaxDynamicSharedMemorySize, (int)sm3);
    cudaFuncSetAttribute(fold0_kernel, cudaFuncAttributeMaxDynamicSharedMemorySize, (int)smf);

    const int EG = (BB*EE/4 + 255) / 256;   // grid for 4-edge-per-thread kernels
    bool fork = g_side.ok;

    // init on main stream (zeroes g_cnt/g_stat used by both branches)
    init_kernel<<<TOT/256 + 1, 256>>>(b02, Wc, bc, b1, b2);

    if (fork) {
        // fork: CSR build on side stream, GEMM chain on main stream
        cudaEventRecord(g_side.eFork, 0);
        cudaStreamWaitEvent(g_side.s, g_side.eFork, 0);
        count_kernel<<<EG, 256, 0, g_side.s>>>(erow);
        scan_kernel<<<BB, 1024, 0, g_side.s>>>();
        scatter_kernel<<<EG, 256, 0, g_side.s>>>(erow, ecol, evl);
        cudaEventRecord(g_side.eJoin, g_side.s);
    } else {
        count_kernel<<<EG, 256>>>(erow);
        scan_kernel<<<BB, 1024>>>();
        scatter_kernel<<<EG, 256>>>(erow, ecol, evl);
    }

    // main chain: h0 = relu(x@W0 + b0) with bn0 stats
    gemm_kernel<FIN,HH,true,0,false><<<TOT/128, 256, sm1>>>(x, W0, b0, p_h0);
    // fused fold: Wa = diag(s0)*(W02@Wc), ba += t0@(W02@Wc)
    fold0_kernel<<<HH, HH, smf>>>(bn0w, bn0b, W02, Wc);
    // hc = h0 @ Wa + ba   (fp16x2 output)
    gemm_kernel<HH,HH,false,-1,true><<<TOT/128, 256, sm2>>>(p_h0, p_Wa, p_ba, p_hcp);

    if (fork) cudaStreamWaitEvent(0, g_side.eJoin, 0);   // join CSR branch

    // SGC aggregate (+mask, relu, bnc stats)
    agg_kernel<<<TOT/8, 128>>>(nn);

    // fold bnc into W1 (bb pre-seeded with b1)
    fold_kernel<HH><<<HH, 128>>>(bncw, bncb, 1, W1, p_Wb, p_bb);

    // h2 = relu(h1 @ Wb + bb), bn1 stats fused
    gemm_kernel<HH,HH,true,2,false><<<TOT/128, 256, sm2>>>(p_h1, p_Wb, p_bb, p_h2);

    // fold bn1 into W2 (bo pre-seeded with b2)
    fold_kernel<FOUT><<<HH, 128>>>(bn1w, bn1b, 2, W2, p_Wo, p_bo);

    // out = h2 @ Wo + bo
    gemm_kernel<HH,FOUT,false,-1,false><<<TOT/128, 256, sm3>>>(p_h2, p_Wo, p_bo, out);
}

// round 12
// speedup vs baseline: 1.8147x; 1.4018x over previous
#include <cuda_runtime.h>
#include <cuda_fp16.h>
#include <cstdint>

#define BB   8
#define NN   8192
#define EE   262144
#define FIN  64
#define HH   128
#define FOUT 32
#define TOT  (BB*NN)   // 65536 rows total

typedef unsigned long long ull;
typedef unsigned int uint;

// ---------------- device scratch (no allocations allowed) ----------------
__device__ float g_h0[(size_t)TOT*HH];
__device__ uint  g_hcp[(size_t)TOT*(HH/2)];   // hc as fp16x2 pairs
__device__ float g_h1[(size_t)TOT*HH];
__device__ float g_h2[(size_t)TOT*HH];
__device__ int   g_cnt[TOT];
__device__ int   g_cursor[TOT];
__device__ int   g_rowstart[TOT];
__device__ uint  g_epk[(size_t)BB*EE];        // packed edge: [fp16 val | 16-bit col]
__device__ float g_stat[6*HH];                // [stage][sum|sumsq][H], stages 0..2
__device__ float g_Wa[HH*HH];
__device__ float g_ba[HH];
__device__ float g_Wb[HH*HH];
__device__ float g_bb[HH];
__device__ float g_Wo[HH*FOUT];
__device__ float g_bo[FOUT];
// fragment-order split-fp16 weight tables: uint4 {bh0,bh1,bl0,bl1} per (ntile,kstep,lane)
__device__ uint4 g_bf0[(HH/8)*(FIN/16)*32];   // W0:  K=64,  N=128
__device__ uint4 g_bfa[(HH/8)*(HH/16)*32];    // Wa:  K=128, N=128
__device__ uint4 g_bfb[(HH/8)*(HH/16)*32];    // Wb:  K=128, N=128
__device__ uint4 g_bfo[(FOUT/8)*(HH/16)*32];  // Wo:  K=128, N=32

// ---------------- side stream for fork-join overlap (created pre-main) -----------
struct SideCtx {
    cudaStream_t s = 0;
    cudaEvent_t  eFork = 0, eJoin = 0;
    bool ok = false;
    SideCtx() {
        ok = (cudaStreamCreateWithFlags(&s, cudaStreamNonBlocking) == cudaSuccess) &&
             (cudaEventCreateWithFlags(&eFork, cudaEventDisableTiming) == cudaSuccess) &&
             (cudaEventCreateWithFlags(&eJoin, cudaEventDisableTiming) == cudaSuccess);
    }
};
static SideCtx g_side;

__device__ __forceinline__ float2 h2f(uint p) {
    return __half22float2(*reinterpret_cast<__half2*>(&p));
}
__device__ __forceinline__ void mma16816(float* d, const uint* a, uint b0, uint b1) {
    asm volatile("mma.sync.aligned.m16n8k16.row.col.f32.f16.f16.f32 "
        "{%0,%1,%2,%3}, {%4,%5,%6,%7}, {%8,%9}, {%0,%1,%2,%3};\n"
        : "+f"(d[0]), "+f"(d[1]), "+f"(d[2]), "+f"(d[3])
        : "r"(a[0]), "r"(a[1]), "r"(a[2]), "r"(a[3]), "r"(b0), "r"(b1));
}
// BN affine coefficients from accumulated stats
__device__ __forceinline__ void bn_st(int stage, int f, const float* bnw, const float* bnb,
                                      float& s, float& t) {
    float cnt = (float)TOT;
    float sum = g_stat[stage*2*HH + f];
    float sq  = g_stat[stage*2*HH + HH + f];
    float m = sum / cnt;
    float v = sq / cnt - m*m;
    float inv = rsqrtf(v + 1e-5f);
    s = bnw[f] * inv;
    t = bnb[f] - m * s;
}

// ---------------- init: zero accumulators, seed fused biases ----------------
__global__ void init_kernel(const float* __restrict__ b02, const float* __restrict__ Wc,
                            const float* __restrict__ bc,  const float* __restrict__ b1,
                            const float* __restrict__ b2)
{
    int gid = blockIdx.x * 256 + threadIdx.x;
    if (gid < TOT) g_cnt[gid] = 0;
    if (gid < 6*HH) g_stat[gid] = 0.f;
    if (blockIdx.x == gridDim.x - 1) {
        int k = threadIdx.x;
        if (k < HH) {
            float s = bc[k];
            #pragma unroll 8
            for (int f = 0; f < HH; f++) s += b02[f] * Wc[f*HH + k];
            g_ba[k] = s;          // (b02 @ Wc + bc); fold0 adds t0 @ (W02@Wc)
            g_bb[k] = b1[k];      // fold1 adds t1 @ W1
        }
        if (k < FOUT) g_bo[k] = b2[k];   // fold2 adds t2 @ W2
    }
}

// ---------------- fused BN0-fold + W02@Wc: Wa[f,:] = s0[f]*(W02[f,:]@Wc) ------------
__global__ void fold0_kernel(const float* __restrict__ bnw, const float* __restrict__ bnb,
                             const float* __restrict__ W02, const float* __restrict__ Wc)
{
    extern __shared__ float sh[];               // [HH*HH] Wc + [HH] w02 row + 2
    float* Wcs = sh;
    float* row = sh + HH*HH;
    float* stp = sh + HH*HH + HH;
    int f = blockIdx.x, k = threadIdx.x;

    #pragma unroll 8
    for (int i = k; i < HH*HH/4; i += HH) ((float4*)Wcs)[i] = ((const float4*)Wc)[i];
    row[k] = W02[f*HH + k];
    if (k == 0) { float s, t; bn_st(0, f, bnw, bnb, s, t); stp[0] = s; stp[1] = t; }
    __syncthreads();

    float m = 0.f;
    #pragma unroll 8
    for (int j = 0; j < HH; j++) m = fmaf(row[j], Wcs[j*HH + k], m);
    g_Wa[f*HH + k] = stp[0] * m;
    atomicAdd(&g_ba[k], stp[1] * m);
}

// ---------------- parallel BN fold ----------------
template<int NC>
__global__ void fold_kernel(const float* __restrict__ bnw, const float* __restrict__ bnb,
                            int stage, const float* __restrict__ Msrc,
                            float* __restrict__ Wdst, float* __restrict__ bias)
{
    __shared__ float stp[2];
    int f = blockIdx.x, k = threadIdx.x;
    if (k == 0) { float s, t; bn_st(stage, f, bnw, bnb, s, t); stp[0] = s; stp[1] = t; }
    __syncthreads();
    if (k < NC) {
        float m = Msrc[f*NC + k];
        Wdst[f*NC + k] = stp[0] * m;
        atomicAdd(&bias[k], stp[1] * m);
    }
}

// ---------------- weight -> split-fp16 mma B-fragment table ----------------
// W is [K][N] row-major fp32. out[(nt*KS+ks)*32 + lane] = {bh0,bh1,bl0,bl1}
// b0 = {W[k0+2t][n], W[k0+2t+1][n]}, b1 = rows +8,+9 (m16n8k16 B layout, col n = nt*8+g)
template<int K, int N>
__global__ void bfrag_kernel(const float* __restrict__ W, uint4* __restrict__ out)
{
    constexpr int KS = K/16;
    int nt = blockIdx.x, ks = blockIdx.y, lane = threadIdx.x;
    int g = lane >> 2, t = lane & 3;
    int n = nt*8 + g, k0 = ks*16 + 2*t;
    float w00 = W[(k0+0)*N + n], w01 = W[(k0+1)*N + n];
    float w10 = W[(k0+8)*N + n], w11 = W[(k0+9)*N + n];
    __half h00 = __float2half_rn(w00), h01 = __float2half_rn(w01);
    __half h10 = __float2half_rn(w10), h11 = __float2half_rn(w11);
    __half l00 = __float2half_rn(w00 - __half2float(h00));
    __half l01 = __float2half_rn(w01 - __half2float(h01));
    __half l10 = __float2half_rn(w10 - __half2float(h10));
    __half l11 = __float2half_rn(w11 - __half2float(h11));
    __half2 bh0 = __halves2half2(h00, h01), bh1 = __halves2half2(h10, h11);
    __half2 bl0 = __halves2half2(l00, l01), bl1 = __halves2half2(l10, l11);
    uint4 v;
    v.x = *(uint*)&bh0; v.y = *(uint*)&bh1; v.z = *(uint*)&bl0; v.w = *(uint*)&bl1;
    out[(nt*KS + ks)*32 + lane] = v;
}

// ---------------- CSR build (4 edges per thread for MLP) ----------------
__global__ void count_kernel(const int* __restrict__ rows)
{
    int gid = blockIdx.x * 256 + threadIdx.x;        // grid covers (BB*EE)/4
    int e0 = gid * 4;
    if (e0 >= BB*EE) return;
    int base = (e0 >> 18) * NN;                      // 4 edges never cross a batch
    int4 r = *(const int4*)(rows + e0);
    atomicAdd(&g_cnt[base + r.x], 1);
    atomicAdd(&g_cnt[base + r.y], 1);
    atomicAdd(&g_cnt[base + r.z], 1);
    atomicAdd(&g_cnt[base + r.w], 1);
}

__global__ void scan_kernel()          // grid=8 (batches), block=1024
{
    int b = blockIdx.x, t = threadIdx.x;
    int base = b*NN + t*8;
    int v[8], pre[8], tot = 0;
    #pragma unroll
    for (int i = 0; i < 8; i++) { v[i] = g_cnt[base+i]; pre[i] = tot; tot += v[i]; }
    int lane = t & 31, w = t >> 5;
    int x = tot;
    #pragma unroll
    for (int o = 1; o < 32; o <<= 1) { int y = __shfl_up_sync(0xffffffffu, x, o); if (lane >= o) x += y; }
    __shared__ int wsum[32];
    if (lane == 31) wsum[w] = x;
    __syncthreads();
    if (w == 0) {
        int y = wsum[lane];
        #pragma unroll
        for (int o = 1; o < 32; o <<= 1) { int z = __shfl_up_sync(0xffffffffu, y, o); if (lane >= o) y += z; }
        wsum[lane] = y;
    }
    __syncthreads();
    int ex = x - tot + (w > 0 ? wsum[w-1] : 0);
    #pragma unroll
    for (int i = 0; i < 8; i++) {
        int st = ex + pre[i];
        g_rowstart[base+i] = st;
        g_cursor[base+i]  = st;
    }
}

__global__ void scatter_kernel(const int* __restrict__ rows, const int* __restrict__ cols,
                               const float* __restrict__ vals)
{
    int gid = blockIdx.x * 256 + threadIdx.x;        // grid covers (BB*EE)/4
    int e0 = gid * 4;
    if (e0 >= BB*EE) return;
    int b = e0 >> 18;
    int base = b * NN;
    size_t ebase = (size_t)b * EE;
    int4   r = *(const int4*)(rows + e0);
    int4   c = *(const int4*)(cols + e0);
    float4 v = *(const float4*)(vals + e0);
    int p0 = atomicAdd(&g_cursor[base + r.x], 1);
    int p1 = atomicAdd(&g_cursor[base + r.y], 1);
    int p2 = atomicAdd(&g_cursor[base + r.z], 1);
    int p3 = atomicAdd(&g_cursor[base + r.w], 1);
    uint h0 = (uint)__half_as_ushort(__float2half_rn(v.x));
    uint h1 = (uint)__half_as_ushort(__float2half_rn(v.y));
    uint h2 = (uint)__half_as_ushort(__float2half_rn(v.z));
    uint h3 = (uint)__half_as_ushort(__float2half_rn(v.w));
    g_epk[ebase + p0] = (h0 << 16) | (uint)c.x;
    g_epk[ebase + p1] = (h1 << 16) | (uint)c.y;
    g_epk[ebase + p2] = (h2 << 16) | (uint)c.z;
    g_epk[ebase + p3] = (h3 << 16) | (uint)c.w;
}

// ---------------- SpMM aggregate (fp16 gather) + norm + mask + relu + bnc stats --------
__global__ void agg_kernel(const int* __restrict__ nn)
{
    __shared__ float s_ls[HH], s_lq[HH];
    int tid = threadIdx.x, w = tid >> 5, lane = tid & 31;
    for (int i = tid; i < HH; i += 128) { s_ls[i] = 0.f; s_lq[i] = 0.f; }
    __syncthreads();

    float ls[4] = {0,0,0,0}, lq[4] = {0,0,0,0};
    #pragma unroll 1
    for (int ri = 0; ri < 2; ri++) {
        int idx = blockIdx.x * 8 + ri*4 + w;
        int b = idx >> 13, r = idx & (NN - 1);
        int start = g_rowstart[idx], len = g_cnt[idx];
        const uint2* hcb = (const uint2*)g_hcp + (size_t)b*NN*32;
        const uint*  ep  = g_epk + (size_t)b*EE + start;

        float a0=0.f, a1=0.f, a2=0.f, a3=0.f, ds=0.f;
        for (int e0 = 0; e0 < len; e0 += 32) {
            uint my = (e0 + lane < len) ? ep[e0 + lane] : 0u;
            int m = min(32, len - e0);
            int t = 0;
            for (; t + 2 <= m; t += 2) {
                uint ea = __shfl_sync(0xffffffffu, my, t);
                uint eb = __shfl_sync(0xffffffffu, my, t+1);
                float va = __half2float(__ushort_as_half((unsigned short)(ea >> 16)));
                float vb = __half2float(__ushort_as_half((unsigned short)(eb >> 16)));
                uint2 ha = hcb[(size_t)(ea & 0xFFFFu)*32 + lane];
                uint2 hb = hcb[(size_t)(eb & 0xFFFFu)*32 + lane];
                float2 fa0 = h2f(ha.x), fa1 = h2f(ha.y);
                float2 fb0 = h2f(hb.x), fb1 = h2f(hb.y);
                a0 = fmaf(va, fa0.x, a0);  a1 = fmaf(va, fa0.y, a1);
                a2 = fmaf(va, fa1.x, a2);  a3 = fmaf(va, fa1.y, a3);
                a0 = fmaf(vb, fb0.x, a0);  a1 = fmaf(vb, fb0.y, a1);
                a2 = fmaf(vb, fb1.x, a2);  a3 = fmaf(vb, fb1.y, a3);
                ds += va + vb;
            }
            if (t < m) {
                uint ea = __shfl_sync(0xffffffffu, my, t);
                float va = __half2float(__ushort_as_half((unsigned short)(ea >> 16)));
                uint2 ha = hcb[(size_t)(ea & 0xFFFFu)*32 + lane];
                float2 fa0 = h2f(ha.x), fa1 = h2f(ha.y);
                a0 = fmaf(va, fa0.x, a0);  a1 = fmaf(va, fa0.y, a1);
                a2 = fmaf(va, fa1.x, a2);  a3 = fmaf(va, fa1.y, a3);
                ds += va;
            }
        }
        float inv = 1.f / fmaxf(ds, 1.f);
        bool dead = (r >= nn[b]);
        float4 o;
        o.x = dead ? 0.f : fmaxf(a0*inv, 0.f);
        o.y = dead ? 0.f : fmaxf(a1*inv, 0.f);
        o.z = dead ? 0.f : fmaxf(a2*inv, 0.f);
        o.w = dead ? 0.f : fmaxf(a3*inv, 0.f);
        *(float4*)&g_h1[(size_t)idx*HH + lane*4] = o;
        ls[0]+=o.x; lq[0]+=o.x*o.x;  ls[1]+=o.y; lq[1]+=o.y*o.y;
        ls[2]+=o.z; lq[2]+=o.z*o.z;  ls[3]+=o.w; lq[3]+=o.w*o.w;
    }
    #pragma unroll
    for (int q = 0; q < 4; q++) {
        atomicAdd(&s_ls[lane*4+q], ls[q]);
        atomicAdd(&s_lq[lane*4+q], lq[q]);
    }
    __syncthreads();
    for (int i = tid; i < HH; i += 128) {
        atomicAdd(&g_stat[1*2*HH + i],      s_ls[i]);
        atomicAdd(&g_stat[1*2*HH + HH + i], s_lq[i]);
    }
}

// ---------------- tensor-core GEMM, 3-term split fp16 (error ~ fp32) ----------------
// C[M,NC] = A[M,K] @ W[K,NC] + bias.  Block: 128 rows, 256 threads (8 warps).
// A split into smem Ah/Al (fp16 hi + residual); W pre-split in fragment order (BF).
template<int K, int NC, bool RELU, int STAGE, bool OUT16>   // STAGE<0: no stats
__global__ __launch_bounds__(256, 2)
void gemm_tc(const float* __restrict__ A, const uint4* __restrict__ BF,
             const float* __restrict__ bias, void* __restrict__ Cv)
{
    constexpr int KS  = K / 16;
    constexpr int WM  = (NC >= 128) ? 4 : 8;    // warps along M
    constexpr int WN  = 8 / WM;                 // warps along N
    constexpr int MF  = 128 / WM / 16;          // m16 frags per warp (2 or 1)
    constexpr int NF  = NC / WN / 8;            // n8 frags per warp (8 or 4)
    constexpr int AST = K + 8;                  // half stride: 2*AST % 128B == 16

    extern __shared__ __half sh2[];
    __half* Ah = sh2;                           // [128][AST]
    __half* Al = sh2 + 128*AST;
    __shared__ float s_ls[HH], s_lq[HH];

    int tid = threadIdx.x;
    size_t row0 = (size_t)blockIdx.x * 128;

    // load A tile, split into hi/lo fp16
    const float4* Ag = (const float4*)(A + row0*K);
    #pragma unroll 4
    for (int i = tid; i < 128*K/4; i += 256) {
        float4 v = Ag[i];
        int r = (i*4)/K, c = (i*4)%K;
        __half h0 = __float2half_rn(v.x), h1 = __float2half_rn(v.y);
        __half h2v = __float2half_rn(v.z), h3 = __float2half_rn(v.w);
        __half* ap = Ah + r*AST + c;
        ap[0] = h0; ap[1] = h1; ap[2] = h2v; ap[3] = h3;
        __half* lp = Al + r*AST + c;
        lp[0] = __float2half_rn(v.x - __half2float(h0));
        lp[1] = __float2half_rn(v.y - __half2float(h1));
        lp[2] = __float2half_rn(v.z - __half2float(h2v));
        lp[3] = __float2half_rn(v.w - __half2float(h3));
    }
    if (STAGE >= 0) for (int i = tid; i < HH; i += 256) { s_ls[i] = 0.f; s_lq[i] = 0.f; }
    __syncthreads();

    int wid = tid >> 5, lane = tid & 31;
    int wm = wid % WM, wn = wid / WM;
    int g = lane >> 2, t = lane & 3;

    float acc[MF][NF][4];
    #pragma unroll
    for (int mf = 0; mf < MF; mf++)
        #pragma unroll
        for (int nf = 0; nf < NF; nf++)
            #pragma unroll
            for (int q = 0; q < 4; q++) acc[mf][nf][q] = 0.f;

    const __half* AhB = Ah + (wm*MF*16)*AST;
    const __half* AlB = Al + (wm*MF*16)*AST;

    #pragma unroll
    for (int ks = 0; ks < KS; ks++) {
        uint ah[MF][4], al[MF][4];
        #pragma unroll
        for (int mf = 0; mf < MF; mf++) {
            int r0 = mf*16 + g, r1 = r0 + 8;
            int c0 = ks*16 + 2*t, c1 = c0 + 8;
            ah[mf][0] = *(const uint*)(AhB + r0*AST + c0);
            ah[mf][1] = *(const uint*)(AhB + r1*AST + c0);
            ah[mf][2] = *(const uint*)(AhB + r0*AST + c1);
            ah[mf][3] = *(const uint*)(AhB + r1*AST + c1);
            al[mf][0] = *(const uint*)(AlB + r0*AST + c0);
            al[mf][1] = *(const uint*)(AlB + r1*AST + c0);
            al[mf][2] = *(const uint*)(AlB + r0*AST + c1);
            al[mf][3] = *(const uint*)(AlB + r1*AST + c1);
        }
        #pragma unroll
        for (int nf = 0; nf < NF; nf++) {
            int nt = wn*NF + nf;
            uint4 b = BF[(nt*KS + ks)*32 + lane];
            #pragma unroll
            for (int mf = 0; mf < MF; mf++) {
                mma16816(acc[mf][nf], ah[mf], b.x, b.y);   // Ah @ Wh
                mma16816(acc[mf][nf], ah[mf], b.z, b.w);   // Ah @ Wl
                mma16816(acc[mf][nf], al[mf], b.x, b.y);   // Al @ Wh
            }
        }
    }

    // epilogue: bias, relu, store, stats
    #pragma unroll
    for (int nf = 0; nf < NF; nf++) {
        int c = wn*NF*8 + nf*8 + 2*t;
        float b0v = bias[c], b1v = bias[c+1];
        float ls0 = 0.f, lq0 = 0.f, ls1 = 0.f, lq1 = 0.f;
        #pragma unroll
        for (int mf = 0; mf < MF; mf++) {
            float v00 = acc[mf][nf][0] + b0v, v01 = acc[mf][nf][1] + b1v;
            float v10 = acc[mf][nf][2] + b0v, v11 = acc[mf][nf][3] + b1v;
            if (RELU) {
                v00 = fmaxf(v00, 0.f); v01 = fmaxf(v01, 0.f);
                v10 = fmaxf(v10, 0.f); v11 = fmaxf(v11, 0.f);
            }
            size_t r0 = row0 + wm*MF*16 + mf*16 + g, r1 = r0 + 8;
            if (OUT16) {
                __half2 p0 = __float22half2_rn(make_float2(v00, v01));
                __half2 p1 = __float22half2_rn(make_float2(v10, v11));
                ((uint*)Cv)[r0*(NC/2) + c/2] = *(uint*)&p0;
                ((uint*)Cv)[r1*(NC/2) + c/2] = *(uint*)&p1;
            } else {
                *(float2*)&((float*)Cv)[r0*NC + c] = make_float2(v00, v01);
                *(float2*)&((float*)Cv)[r1*NC + c] = make_float2(v10, v11);
            }
            if (STAGE >= 0) {
                ls0 += v00 + v10; lq0 += v00*v00 + v10*v10;
                ls1 += v01 + v11; lq1 += v01*v01 + v11*v11;
            }
        }
        if (STAGE >= 0) {
            // reduce across g (lane bits 2..4), then 4 lanes commit
            #pragma unroll
            for (int o = 4; o <= 16; o <<= 1) {
                ls0 += __shfl_xor_sync(0xffffffffu, ls0, o);
                lq0 += __shfl_xor_sync(0xffffffffu, lq0, o);
                ls1 += __shfl_xor_sync(0xffffffffu, ls1, o);
                lq1 += __shfl_xor_sync(0xffffffffu, lq1, o);
            }
            if (lane < 4) {
                atomicAdd(&s_ls[c], ls0); atomicAdd(&s_lq[c], lq0);
                atomicAdd(&s_ls[c+1], ls1); atomicAdd(&s_lq[c+1], lq1);
            }
        }
    }

    if (STAGE >= 0) {
        __syncthreads();
        for (int i = tid; i < NC; i += 256) {
            atomicAdd(&g_stat[STAGE*2*HH + i],      s_ls[i]);
            atomicAdd(&g_stat[STAGE*2*HH + HH + i], s_lq[i]);
        }
    }
}

// ---------------- host launcher ----------------
extern "C" void kernel_launch(void* const* d_in, const int* in_sizes, int n_in,
                              void* d_out, int out_size)
{
    const float* x    = (const float*)d_in[0];
    const int*   erow = (const int*)  d_in[1];
    const int*   ecol = (const int*)  d_in[2];
    const float* evl  = (const float*)d_in[3];
    const int*   nn   = (const int*)  d_in[4];
    const float* W0   = (const float*)d_in[5];
    const float* b0   = (const float*)d_in[6];
    const float* W02  = (const float*)d_in[7];
    const float* b02  = (const float*)d_in[8];
    const float* Wc   = (const float*)d_in[9];
    const float* bc   = (const float*)d_in[10];
    const float* W1   = (const float*)d_in[11];
    const float* b1   = (const float*)d_in[12];
    const float* W2   = (const float*)d_in[13];
    const float* b2   = (const float*)d_in[14];
    const float* bn0w = (const float*)d_in[15];
    const float* bn0b = (const float*)d_in[16];
    const float* bncw = (const float*)d_in[17];
    const float* bncb = (const float*)d_in[18];
    const float* bn1w = (const float*)d_in[19];
    const float* bn1b = (const float*)d_in[20];
    float* out = (float*)d_out;

    float *p_h0, *p_h1, *p_h2, *p_Wa, *p_ba, *p_Wb, *p_bb, *p_Wo, *p_bo;
    uint  *p_hcp;
    uint4 *p_bf0, *p_bfa, *p_bfb, *p_bfo;
    cudaGetSymbolAddress((void**)&p_h0,  g_h0);
    cudaGetSymbolAddress((void**)&p_hcp, g_hcp);
    cudaGetSymbolAddress((void**)&p_h1,  g_h1);
    cudaGetSymbolAddress((void**)&p_h2,  g_h2);
    cudaGetSymbolAddress((void**)&p_Wa,  g_Wa);
    cudaGetSymbolAddress((void**)&p_ba,  g_ba);
    cudaGetSymbolAddress((void**)&p_Wb,  g_Wb);
    cudaGetSymbolAddress((void**)&p_bb,  g_bb);
    cudaGetSymbolAddress((void**)&p_Wo,  g_Wo);
    cudaGetSymbolAddress((void**)&p_bo,  g_bo);
    cudaGetSymbolAddress((void**)&p_bf0, g_bf0);
    cudaGetSymbolAddress((void**)&p_bfa, g_bfa);
    cudaGetSymbolAddress((void**)&p_bfb, g_bfb);
    cudaGetSymbolAddress((void**)&p_bfo, g_bfo);

    const size_t smA1 = (size_t)2 * 128 * (FIN + 8) * sizeof(__half);   // K=64
    const size_t smA2 = (size_t)2 * 128 * (HH  + 8) * sizeof(__half);   // K=128
    const size_t smf  = ((size_t)HH*HH + HH + 2) * sizeof(float);
    cudaFuncSetAttribute(gemm_tc<FIN,HH,true,0,false>,    cudaFuncAttributeMaxDynamicSharedMemorySize, (int)smA1);
    cudaFuncSetAttribute(gemm_tc<HH,HH,false,-1,true>,    cudaFuncAttributeMaxDynamicSharedMemorySize, (int)smA2);
    cudaFuncSetAttribute(gemm_tc<HH,HH,true,2,false>,     cudaFuncAttributeMaxDynamicSharedMemorySize, (int)smA2);
    cudaFuncSetAttribute(gemm_tc<HH,FOUT,false,-1,false>, cudaFuncAttributeMaxDynamicSharedMemorySize, (int)smA2);
    cudaFuncSetAttribute(fold0_kernel, cudaFuncAttributeMaxDynamicSharedMemorySize, (int)smf);

    const int EG = (BB*EE/4 + 255) / 256;   // grid for 4-edge-per-thread kernels
    bool fork = g_side.ok;

    // init on main stream (zeroes g_cnt/g_stat used by both branches)
    init_kernel<<<TOT/256 + 1, 256>>>(b02, Wc, bc, b1, b2);

    if (fork) {
        // fork: CSR build on side stream, GEMM chain on main stream
        cudaEventRecord(g_side.eFork, 0);
        cudaStreamWaitEvent(g_side.s, g_side.eFork, 0);
        count_kernel<<<EG, 256, 0, g_side.s>>>(erow);
        scan_kernel<<<BB, 1024, 0, g_side.s>>>();
        scatter_kernel<<<EG, 256, 0, g_side.s>>>(erow, ecol, evl);
        cudaEventRecord(g_side.eJoin, g_side.s);
    } else {
        count_kernel<<<EG, 256>>>(erow);
        scan_kernel<<<BB, 1024>>>();
        scatter_kernel<<<EG, 256>>>(erow, ecol, evl);
    }

    // main chain: h0 = relu(x@W0 + b0) with bn0 stats
    bfrag_kernel<FIN,HH><<<dim3(HH/8, FIN/16), 32>>>(W0, p_bf0);
    gemm_tc<FIN,HH,true,0,false><<<TOT/128, 256, smA1>>>(x, p_bf0, b0, p_h0);

    // fused fold: Wa = diag(s0)*(W02@Wc), ba += t0@(W02@Wc)
    fold0_kernel<<<HH, HH, smf>>>(bn0w, bn0b, W02, Wc);
    bfrag_kernel<HH,HH><<<dim3(HH/8, HH/16), 32>>>(p_Wa, p_bfa);

    // hc = h0 @ Wa + ba   (fp16x2 output)
    gemm_tc<HH,HH,false,-1,true><<<TOT/128, 256, smA2>>>(p_h0, p_bfa, p_ba, p_hcp);

    if (fork) cudaStreamWaitEvent(0, g_side.eJoin, 0);   // join CSR branch

    // SGC aggregate (+mask, relu, bnc stats)
    agg_kernel<<<TOT/8, 128>>>(nn);

    // fold bnc into W1 (bb pre-seeded with b1)
    fold_kernel<HH><<<HH, 128>>>(bncw, bncb, 1, W1, p_Wb, p_bb);
    bfrag_kernel<HH,HH><<<dim3(HH/8, HH/16), 32>>>(p_Wb, p_bfb);

    // h2 = relu(h1 @ Wb + bb), bn1 stats fused
    gemm_tc<HH,HH,true,2,false><<<TOT/128, 256, smA2>>>(p_h1, p_bfb, p_bb, p_h2);

    // fold bn1 into W2 (bo pre-seeded with b2)
    fold_kernel<FOUT><<<HH, 128>>>(bn1w, bn1b, 2, W2, p_Wo, p_bo);
    bfrag_kernel<HH,FOUT><<<dim3(FOUT/8, HH/16), 32>>>(p_Wo, p_bfo);

    // out = h2 @ Wo + bo
    gemm_tc<HH,FOUT,false,-1,false><<<TOT/128, 256, smA2>>>(p_h2, p_bfo, p_bo, out);
}

// round 13
// speedup vs baseline: 1.9253x; 1.0610x over previous
#include <cuda_runtime.h>
#include <cuda_fp16.h>
#include <cstdint>

#define BB   8
#define NN   8192
#define EE   262144
#define FIN  64
#define HH   128
#define FOUT 32
#define TOT  (BB*NN)   // 65536 rows total
#define CAP  128       // bucket capacity; deg ~ Poisson(32), max over 65K rows ~ 70

typedef unsigned long long ull;
typedef unsigned int uint;

// ---------------- device scratch (no allocations allowed) ----------------
__device__ float g_h0[(size_t)TOT*HH];
__device__ uint  g_hcp[(size_t)TOT*(HH/2)];   // hc as fp16x2 pairs
__device__ float g_h1[(size_t)TOT*HH];
__device__ float g_h2[(size_t)TOT*HH];
__device__ int   g_cnt[TOT];
__device__ uint  g_bkt[(size_t)TOT*CAP];      // bucketed edges: [fp16 val | 16-bit col]
__device__ float g_stat[6*HH];                // [stage][sum|sumsq][H], stages 0..2
__device__ float g_Wa[HH*HH];
__device__ float g_ba[HH];
__device__ float g_bb[HH];
__device__ float g_bo[FOUT];
// fragment-order split-fp16 weight tables: uint4 {bh0,bh1,bl0,bl1} per (ntile,kstep,lane)
__device__ uint4 g_bf0[(HH/8)*(FIN/16)*32];   // W0:  K=64,  N=128
__device__ uint4 g_bfa[(HH/8)*(HH/16)*32];    // Wa:  K=128, N=128
__device__ uint4 g_bfb[(HH/8)*(HH/16)*32];    // Wb:  K=128, N=128
__device__ uint4 g_bfo[(FOUT/8)*(HH/16)*32];  // Wo:  K=128, N=32

// ---------------- side stream for fork-join overlap (created pre-main) -----------
struct SideCtx {
    cudaStream_t s = 0;
    cudaEvent_t  eFork = 0, eJoin = 0;
    bool ok = false;
    SideCtx() {
        ok = (cudaStreamCreateWithFlags(&s, cudaStreamNonBlocking) == cudaSuccess) &&
             (cudaEventCreateWithFlags(&eFork, cudaEventDisableTiming) == cudaSuccess) &&
             (cudaEventCreateWithFlags(&eJoin, cudaEventDisableTiming) == cudaSuccess);
    }
};
static SideCtx g_side;

__device__ __forceinline__ float2 h2f(uint p) {
    return __half22float2(*reinterpret_cast<__half2*>(&p));
}
__device__ __forceinline__ void mma16816(float* d, const uint* a, uint b0, uint b1) {
    asm volatile("mma.sync.aligned.m16n8k16.row.col.f32.f16.f16.f32 "
        "{%0,%1,%2,%3}, {%4,%5,%6,%7}, {%8,%9}, {%0,%1,%2,%3};\n"
        : "+f"(d[0]), "+f"(d[1]), "+f"(d[2]), "+f"(d[3])
        : "r"(a[0]), "r"(a[1]), "r"(a[2]), "r"(a[3]), "r"(b0), "r"(b1));
}
// BN affine coefficients from accumulated stats
__device__ __forceinline__ void bn_st(int stage, int f, const float* bnw, const float* bnb,
                                      float& s, float& t) {
    float cnt = (float)TOT;
    float sum = g_stat[stage*2*HH + f];
    float sq  = g_stat[stage*2*HH + HH + f];
    float m = sum / cnt;
    float v = sq / cnt - m*m;
    float inv = rsqrtf(v + 1e-5f);
    s = bnw[f] * inv;
    t = bnb[f] - m * s;
}

// ---------------- init: zero accumulators, seed fused biases ----------------
__global__ void init_kernel(const float* __restrict__ b02, const float* __restrict__ Wc,
                            const float* __restrict__ bc,  const float* __restrict__ b1,
                            const float* __restrict__ b2)
{
    int gid = blockIdx.x * 256 + threadIdx.x;
    if (gid < TOT) g_cnt[gid] = 0;
    if (gid < 6*HH) g_stat[gid] = 0.f;
    if (blockIdx.x == gridDim.x - 1) {
        int k = threadIdx.x;
        if (k < HH) {
            float s = bc[k];
            #pragma unroll 8
            for (int f = 0; f < HH; f++) s += b02[f] * Wc[f*HH + k];
            g_ba[k] = s;          // (b02 @ Wc + bc); fold0 adds t0 @ (W02@Wc)
            g_bb[k] = b1[k];      // fold_bfrag(1) adds t1 @ W1
        }
        if (k < FOUT) g_bo[k] = b2[k];   // fold_bfrag(2) adds t2 @ W2
    }
}

// ---------------- fused BN0-fold + W02@Wc: Wa[f,:] = s0[f]*(W02[f,:]@Wc) ------------
__global__ void fold0_kernel(const float* __restrict__ bnw, const float* __restrict__ bnb,
                             const float* __restrict__ W02, const float* __restrict__ Wc)
{
    extern __shared__ float sh[];               // [HH*HH] Wc + [HH] w02 row + 2
    float* Wcs = sh;
    float* row = sh + HH*HH;
    float* stp = sh + HH*HH + HH;
    int f = blockIdx.x, k = threadIdx.x;

    #pragma unroll 8
    for (int i = k; i < HH*HH/4; i += HH) ((float4*)Wcs)[i] = ((const float4*)Wc)[i];
    row[k] = W02[f*HH + k];
    if (k == 0) { float s, t; bn_st(0, f, bnw, bnb, s, t); stp[0] = s; stp[1] = t; }
    __syncthreads();

    float m = 0.f;
    #pragma unroll 8
    for (int j = 0; j < HH; j++) m = fmaf(row[j], Wcs[j*HH + k], m);
    g_Wa[f*HH + k] = stp[0] * m;
    atomicAdd(&g_ba[k], stp[1] * m);
}

// ---------------- weight -> split-fp16 mma B-fragment table ----------------
// W is [K][N] row-major fp32. out[(nt*KS+ks)*32 + lane] = {bh0,bh1,bl0,bl1}
template<int K, int N>
__global__ void bfrag_kernel(const float* __restrict__ W, uint4* __restrict__ out)
{
    constexpr int KS = K/16;
    int nt = blockIdx.x, ks = blockIdx.y, lane = threadIdx.x;
    int g = lane >> 2, t = lane & 3;
    int n = nt*8 + g, k0 = ks*16 + 2*t;
    float w00 = W[(k0+0)*N + n], w01 = W[(k0+1)*N + n];
    float w10 = W[(k0+8)*N + n], w11 = W[(k0+9)*N + n];
    __half h00 = __float2half_rn(w00), h01 = __float2half_rn(w01);
    __half h10 = __float2half_rn(w10), h11 = __float2half_rn(w11);
    __half l00 = __float2half_rn(w00 - __half2float(h00));
    __half l01 = __float2half_rn(w01 - __half2float(h01));
    __half l10 = __float2half_rn(w10 - __half2float(h10));
    __half l11 = __float2half_rn(w11 - __half2float(h11));
    __half2 bh0 = __halves2half2(h00, h01), bh1 = __halves2half2(h10, h11);
    __half2 bl0 = __halves2half2(l00, l01), bl1 = __halves2half2(l10, l11);
    uint4 v;
    v.x = *(uint*)&bh0; v.y = *(uint*)&bh1; v.z = *(uint*)&bl0; v.w = *(uint*)&bl1;
    out[(nt*KS + ks)*32 + lane] = v;
}

// ---------------- fused BN-fold + split-fp16 fragment build + bias ----------------
// Wdst[f,n] = s[f]*W[f,n] emitted directly as frag table; bias[n] += sum_f t[f]*W[f,n]
template<int K, int N>
__global__ void fold_bfrag_kernel(const float* __restrict__ bnw, const float* __restrict__ bnb,
                                  int stage, const float* __restrict__ W,
                                  uint4* __restrict__ out, float* __restrict__ bias)
{
    constexpr int KS = K/16;
    int nt = blockIdx.x, ks = blockIdx.y, lane = threadIdx.x;
    int g = lane >> 2, t = lane & 3;
    int n = nt*8 + g, k0 = ks*16 + 2*t;
    float s0,t0,s1,t1,s2,t2,s3,t3;
    bn_st(stage, k0+0, bnw, bnb, s0, t0);
    bn_st(stage, k0+1, bnw, bnb, s1, t1);
    bn_st(stage, k0+8, bnw, bnb, s2, t2);
    bn_st(stage, k0+9, bnw, bnb, s3, t3);
    float m00 = W[(k0+0)*N + n], m01 = W[(k0+1)*N + n];
    float m10 = W[(k0+8)*N + n], m11 = W[(k0+9)*N + n];
    float w00 = s0*m00, w01 = s1*m01, w10 = s2*m10, w11 = s3*m11;
    __half h00 = __float2half_rn(w00), h01 = __float2half_rn(w01);
    __half h10 = __float2half_rn(w10), h11 = __float2half_rn(w11);
    __half l00 = __float2half_rn(w00 - __half2float(h00));
    __half l01 = __float2half_rn(w01 - __half2float(h01));
    __half l10 = __float2half_rn(w10 - __half2float(h10));
    __half l11 = __float2half_rn(w11 - __half2float(h11));
    __half2 bh0 = __halves2half2(h00, h01), bh1 = __halves2half2(h10, h11);
    __half2 bl0 = __halves2half2(l00, l01), bl1 = __halves2half2(l10, l11);
    uint4 v;
    v.x = *(uint*)&bh0; v.y = *(uint*)&bh1; v.z = *(uint*)&bl0; v.w = *(uint*)&bl1;
    out[(nt*KS + ks)*32 + lane] = v;
    // bias contribution, reduced over the 4 t-lanes sharing column n
    float bc = t0*m00 + t1*m01 + t2*m10 + t3*m11;
    bc += __shfl_xor_sync(0xffffffffu, bc, 1);
    bc += __shfl_xor_sync(0xffffffffu, bc, 2);
    if (t == 0) atomicAdd(&bias[n], bc);
}

// ---------------- single-pass bucketed edge build (4 edges/thread) ----------------
__global__ void scatter_kernel(const int* __restrict__ rows, const int* __restrict__ cols,
                               const float* __restrict__ vals)
{
    int gid = blockIdx.x * 256 + threadIdx.x;        // grid covers (BB*EE)/4
    int e0 = gid * 4;
    if (e0 >= BB*EE) return;
    int base = (e0 >> 18) * NN;                      // 4 edges never cross a batch
    int4   r = *(const int4*)(rows + e0);
    int4   c = *(const int4*)(cols + e0);
    float4 v = *(const float4*)(vals + e0);
    int i0 = base + r.x, i1 = base + r.y, i2 = base + r.z, i3 = base + r.w;
    int p0 = atomicAdd(&g_cnt[i0], 1);
    int p1 = atomicAdd(&g_cnt[i1], 1);
    int p2 = atomicAdd(&g_cnt[i2], 1);
    int p3 = atomicAdd(&g_cnt[i3], 1);
    uint h0 = (uint)__half_as_ushort(__float2half_rn(v.x));
    uint h1 = (uint)__half_as_ushort(__float2half_rn(v.y));
    uint h2 = (uint)__half_as_ushort(__float2half_rn(v.z));
    uint h3 = (uint)__half_as_ushort(__float2half_rn(v.w));
    if (p0 < CAP) g_bkt[(size_t)i0*CAP + p0] = (h0 << 16) | (uint)c.x;
    if (p1 < CAP) g_bkt[(size_t)i1*CAP + p1] = (h1 << 16) | (uint)c.y;
    if (p2 < CAP) g_bkt[(size_t)i2*CAP + p2] = (h2 << 16) | (uint)c.z;
    if (p3 < CAP) g_bkt[(size_t)i3*CAP + p3] = (h3 << 16) | (uint)c.w;
}

// ---------------- SpMM aggregate (fp16 gather) + norm + mask + relu + bnc stats --------
__global__ void agg_kernel(const int* __restrict__ nn)
{
    __shared__ float s_ls[HH], s_lq[HH];
    int tid = threadIdx.x, w = tid >> 5, lane = tid & 31;
    for (int i = tid; i < HH; i += 128) { s_ls[i] = 0.f; s_lq[i] = 0.f; }
    __syncthreads();

    float ls[4] = {0,0,0,0}, lq[4] = {0,0,0,0};
    #pragma unroll 1
    for (int ri = 0; ri < 2; ri++) {
        int idx = blockIdx.x * 8 + ri*4 + w;
        int b = idx >> 13, r = idx & (NN - 1);
        int len = min(g_cnt[idx], CAP);
        const uint2* hcb = (const uint2*)g_hcp + (size_t)b*NN*32;
        const uint*  ep  = g_bkt + (size_t)idx*CAP;

        float a0=0.f, a1=0.f, a2=0.f, a3=0.f, ds=0.f;
        for (int e0 = 0; e0 < len; e0 += 32) {
            uint my = (e0 + lane < len) ? ep[e0 + lane] : 0u;
            int m = min(32, len - e0);
            int t = 0;
            for (; t + 2 <= m; t += 2) {
                uint ea = __shfl_sync(0xffffffffu, my, t);
                uint eb = __shfl_sync(0xffffffffu, my, t+1);
                float va = __half2float(__ushort_as_half((unsigned short)(ea >> 16)));
                float vb = __half2float(__ushort_as_half((unsigned short)(eb >> 16)));
                uint2 ha = hcb[(size_t)(ea & 0xFFFFu)*32 + lane];
                uint2 hb = hcb[(size_t)(eb & 0xFFFFu)*32 + lane];
                float2 fa0 = h2f(ha.x), fa1 = h2f(ha.y);
                float2 fb0 = h2f(hb.x), fb1 = h2f(hb.y);
                a0 = fmaf(va, fa0.x, a0);  a1 = fmaf(va, fa0.y, a1);
                a2 = fmaf(va, fa1.x, a2);  a3 = fmaf(va, fa1.y, a3);
                a0 = fmaf(vb, fb0.x, a0);  a1 = fmaf(vb, fb0.y, a1);
                a2 = fmaf(vb, fb1.x, a2);  a3 = fmaf(vb, fb1.y, a3);
                ds += va + vb;
            }
            if (t < m) {
                uint ea = __shfl_sync(0xffffffffu, my, t);
                float va = __half2float(__ushort_as_half((unsigned short)(ea >> 16)));
                uint2 ha = hcb[(size_t)(ea & 0xFFFFu)*32 + lane];
                float2 fa0 = h2f(ha.x), fa1 = h2f(ha.y);
                a0 = fmaf(va, fa0.x, a0);  a1 = fmaf(va, fa0.y, a1);
                a2 = fmaf(va, fa1.x, a2);  a3 = fmaf(va, fa1.y, a3);
                ds += va;
            }
        }
        float inv = 1.f / fmaxf(ds, 1.f);
        bool dead = (r >= nn[b]);
        float4 o;
        o.x = dead ? 0.f : fmaxf(a0*inv, 0.f);
        o.y = dead ? 0.f : fmaxf(a1*inv, 0.f);
        o.z = dead ? 0.f : fmaxf(a2*inv, 0.f);
        o.w = dead ? 0.f : fmaxf(a3*inv, 0.f);
        *(float4*)&g_h1[(size_t)idx*HH + lane*4] = o;
        ls[0]+=o.x; lq[0]+=o.x*o.x;  ls[1]+=o.y; lq[1]+=o.y*o.y;
        ls[2]+=o.z; lq[2]+=o.z*o.z;  ls[3]+=o.w; lq[3]+=o.w*o.w;
    }
    #pragma unroll
    for (int q = 0; q < 4; q++) {
        atomicAdd(&s_ls[lane*4+q], ls[q]);
        atomicAdd(&s_lq[lane*4+q], lq[q]);
    }
    __syncthreads();
    for (int i = tid; i < HH; i += 128) {
        atomicAdd(&g_stat[1*2*HH + i],      s_ls[i]);
        atomicAdd(&g_stat[1*2*HH + HH + i], s_lq[i]);
    }
}

// ---------------- tensor-core GEMM, 3-term split fp16 (error ~ fp32) ----------------
template<int K, int NC, bool RELU, int STAGE, bool OUT16>   // STAGE<0: no stats
__global__ __launch_bounds__(256, 2)
void gemm_tc(const float* __restrict__ A, const uint4* __restrict__ BF,
             const float* __restrict__ bias, void* __restrict__ Cv)
{
    constexpr int KS  = K / 16;
    constexpr int WM  = (NC >= 128) ? 4 : 8;    // warps along M
    constexpr int WN  = 8 / WM;                 // warps along N
    constexpr int MF  = 128 / WM / 16;          // m16 frags per warp (2 or 1)
    constexpr int NF  = NC / WN / 8;            // n8 frags per warp (8 or 4)
    constexpr int AST = K + 8;                  // half stride: 2*AST % 128B == 16

    extern __shared__ __half sh2[];
    __half* Ah = sh2;                           // [128][AST]
    __half* Al = sh2 + 128*AST;
    __shared__ float s_ls[HH], s_lq[HH];

    int tid = threadIdx.x;
    size_t row0 = (size_t)blockIdx.x * 128;

    // load A tile, split into hi/lo fp16
    const float4* Ag = (const float4*)(A + row0*K);
    #pragma unroll 4
    for (int i = tid; i < 128*K/4; i += 256) {
        float4 v = Ag[i];
        int r = (i*4)/K, c = (i*4)%K;
        __half h0 = __float2half_rn(v.x), h1 = __float2half_rn(v.y);
        __half h2v = __float2half_rn(v.z), h3 = __float2half_rn(v.w);
        __half* ap = Ah + r*AST + c;
        ap[0] = h0; ap[1] = h1; ap[2] = h2v; ap[3] = h3;
        __half* lp = Al + r*AST + c;
        lp[0] = __float2half_rn(v.x - __half2float(h0));
        lp[1] = __float2half_rn(v.y - __half2float(h1));
        lp[2] = __float2half_rn(v.z - __half2float(h2v));
        lp[3] = __float2half_rn(v.w - __half2float(h3));
    }
    if (STAGE >= 0) for (int i = tid; i < HH; i += 256) { s_ls[i] = 0.f; s_lq[i] = 0.f; }
    __syncthreads();

    int wid = tid >> 5, lane = tid & 31;
    int wm = wid % WM, wn = wid / WM;
    int g = lane >> 2, t = lane & 3;

    float acc[MF][NF][4];
    #pragma unroll
    for (int mf = 0; mf < MF; mf++)
        #pragma unroll
        for (int nf = 0; nf < NF; nf++)
            #pragma unroll
            for (int q = 0; q < 4; q++) acc[mf][nf][q] = 0.f;

    const __half* AhB = Ah + (wm*MF*16)*AST;
    const __half* AlB = Al + (wm*MF*16)*AST;

    #pragma unroll
    for (int ks = 0; ks < KS; ks++) {
        uint ah[MF][4], al[MF][4];
        #pragma unroll
        for (int mf = 0; mf < MF; mf++) {
            int r0 = mf*16 + g, r1 = r0 + 8;
            int c0 = ks*16 + 2*t, c1 = c0 + 8;
            ah[mf][0] = *(const uint*)(AhB + r0*AST + c0);
            ah[mf][1] = *(const uint*)(AhB + r1*AST + c0);
            ah[mf][2] = *(const uint*)(AhB + r0*AST + c1);
            ah[mf][3] = *(const uint*)(AhB + r1*AST + c1);
            al[mf][0] = *(const uint*)(AlB + r0*AST + c0);
            al[mf][1] = *(const uint*)(AlB + r1*AST + c0);
            al[mf][2] = *(const uint*)(AlB + r0*AST + c1);
            al[mf][3] = *(const uint*)(AlB + r1*AST + c1);
        }
        #pragma unroll
        for (int nf = 0; nf < NF; nf++) {
            int nt = wn*NF + nf;
            uint4 b = BF[(nt*KS + ks)*32 + lane];
            #pragma unroll
            for (int mf = 0; mf < MF; mf++) {
                mma16816(acc[mf][nf], ah[mf], b.x, b.y);   // Ah @ Wh
                mma16816(acc[mf][nf], ah[mf], b.z, b.w);   // Ah @ Wl
                mma16816(acc[mf][nf], al[mf], b.x, b.y);   // Al @ Wh
            }
        }
    }

    // epilogue: bias, relu, store, stats
    #pragma unroll
    for (int nf = 0; nf < NF; nf++) {
        int c = wn*NF*8 + nf*8 + 2*t;
        float b0v = bias[c], b1v = bias[c+1];
        float ls0 = 0.f, lq0 = 0.f, ls1 = 0.f, lq1 = 0.f;
        #pragma unroll
        for (int mf = 0; mf < MF; mf++) {
            float v00 = acc[mf][nf][0] + b0v, v01 = acc[mf][nf][1] + b1v;
            float v10 = acc[mf][nf][2] + b0v, v11 = acc[mf][nf][3] + b1v;
            if (RELU) {
                v00 = fmaxf(v00, 0.f); v01 = fmaxf(v01, 0.f);
                v10 = fmaxf(v10, 0.f); v11 = fmaxf(v11, 0.f);
            }
            size_t r0 = row0 + wm*MF*16 + mf*16 + g, r1 = r0 + 8;
            if (OUT16) {
                __half2 p0 = __float22half2_rn(make_float2(v00, v01));
                __half2 p1 = __float22half2_rn(make_float2(v10, v11));
                ((uint*)Cv)[r0*(NC/2) + c/2] = *(uint*)&p0;
                ((uint*)Cv)[r1*(NC/2) + c/2] = *(uint*)&p1;
            } else {
                *(float2*)&((float*)Cv)[r0*NC + c] = make_float2(v00, v01);
                *(float2*)&((float*)Cv)[r1*NC + c] = make_float2(v10, v11);
            }
            if (STAGE >= 0) {
                ls0 += v00 + v10; lq0 += v00*v00 + v10*v10;
                ls1 += v01 + v11; lq1 += v01*v01 + v11*v11;
            }
        }
        if (STAGE >= 0) {
            #pragma unroll
            for (int o = 4; o <= 16; o <<= 1) {
                ls0 += __shfl_xor_sync(0xffffffffu, ls0, o);
                lq0 += __shfl_xor_sync(0xffffffffu, lq0, o);
                ls1 += __shfl_xor_sync(0xffffffffu, ls1, o);
                lq1 += __shfl_xor_sync(0xffffffffu, lq1, o);
            }
            if (lane < 4) {
                atomicAdd(&s_ls[c], ls0); atomicAdd(&s_lq[c], lq0);
                atomicAdd(&s_ls[c+1], ls1); atomicAdd(&s_lq[c+1], lq1);
            }
        }
    }

    if (STAGE >= 0) {
        __syncthreads();
        for (int i = tid; i < NC; i += 256) {
            atomicAdd(&g_stat[STAGE*2*HH + i],      s_ls[i]);
            atomicAdd(&g_stat[STAGE*2*HH + HH + i], s_lq[i]);
        }
    }
}

// ---------------- host launcher ----------------
extern "C" void kernel_launch(void* const* d_in, const int* in_sizes, int n_in,
                              void* d_out, int out_size)
{
    const float* x    = (const float*)d_in[0];
    const int*   erow = (const int*)  d_in[1];
    const int*   ecol = (const int*)  d_in[2];
    const float* evl  = (const float*)d_in[3];
    const int*   nn   = (const int*)  d_in[4];
    const float* W0   = (const float*)d_in[5];
    const float* b0   = (const float*)d_in[6];
    const float* W02  = (const float*)d_in[7];
    const float* b02  = (const float*)d_in[8];
    const float* Wc   = (const float*)d_in[9];
    const float* bc   = (const float*)d_in[10];
    const float* W1   = (const float*)d_in[11];
    const float* b1   = (const float*)d_in[12];
    const float* W2   = (const float*)d_in[13];
    const float* b2   = (const float*)d_in[14];
    const float* bn0w = (const float*)d_in[15];
    const float* bn0b = (const float*)d_in[16];
    const float* bncw = (const float*)d_in[17];
    const float* bncb = (const float*)d_in[18];
    const float* bn1w = (const float*)d_in[19];
    const float* bn1b = (const float*)d_in[20];
    float* out = (float*)d_out;

    float *p_h0, *p_h1, *p_h2, *p_Wa, *p_ba, *p_bb, *p_bo;
    uint  *p_hcp;
    uint4 *p_bf0, *p_bfa, *p_bfb, *p_bfo;
    cudaGetSymbolAddress((void**)&p_h0,  g_h0);
    cudaGetSymbolAddress((void**)&p_hcp, g_hcp);
    cudaGetSymbolAddress((void**)&p_h1,  g_h1);
    cudaGetSymbolAddress((void**)&p_h2,  g_h2);
    cudaGetSymbolAddress((void**)&p_Wa,  g_Wa);
    cudaGetSymbolAddress((void**)&p_ba,  g_ba);
    cudaGetSymbolAddress((void**)&p_bb,  g_bb);
    cudaGetSymbolAddress((void**)&p_bo,  g_bo);
    cudaGetSymbolAddress((void**)&p_bf0, g_bf0);
    cudaGetSymbolAddress((void**)&p_bfa, g_bfa);
    cudaGetSymbolAddress((void**)&p_bfb, g_bfb);
    cudaGetSymbolAddress((void**)&p_bfo, g_bfo);

    const size_t smA1 = (size_t)2 * 128 * (FIN + 8) * sizeof(__half);   // K=64
    const size_t smA2 = (size_t)2 * 128 * (HH  + 8) * sizeof(__half);   // K=128
    const size_t smf  = ((size_t)HH*HH + HH + 2) * sizeof(float);
    cudaFuncSetAttribute(gemm_tc<FIN,HH,true,0,false>,    cudaFuncAttributeMaxDynamicSharedMemorySize, (int)smA1);
    cudaFuncSetAttribute(gemm_tc<HH,HH,false,-1,true>,    cudaFuncAttributeMaxDynamicSharedMemorySize, (int)smA2);
    cudaFuncSetAttribute(gemm_tc<HH,HH,true,2,false>,     cudaFuncAttributeMaxDynamicSharedMemorySize, (int)smA2);
    cudaFuncSetAttribute(gemm_tc<HH,FOUT,false,-1,false>, cudaFuncAttributeMaxDynamicSharedMemorySize, (int)smA2);
    cudaFuncSetAttribute(fold0_kernel, cudaFuncAttributeMaxDynamicSharedMemorySize, (int)smf);

    const int EG = (BB*EE/4 + 255) / 256;   // grid for 4-edge-per-thread kernels
    bool fork = g_side.ok;

    // init on main stream (zeroes g_cnt/g_stat used by both branches)
    init_kernel<<<TOT/256 + 1, 256>>>(b02, Wc, bc, b1, b2);

    if (fork) {
        // fork: bucketed edge build on side stream, GEMM chain on main stream
        cudaEventRecord(g_side.eFork, 0);
        cudaStreamWaitEvent(g_side.s, g_side.eFork, 0);
        scatter_kernel<<<EG, 256, 0, g_side.s>>>(erow, ecol, evl);
        cudaEventRecord(g_side.eJoin, g_side.s);
    } else {
        scatter_kernel<<<EG, 256>>>(erow, ecol, evl);
    }

    // main chain: h0 = relu(x@W0 + b0) with bn0 stats
    bfrag_kernel<FIN,HH><<<dim3(HH/8, FIN/16), 32>>>(W0, p_bf0);
    gemm_tc<FIN,HH,true,0,false><<<TOT/128, 256, smA1>>>(x, p_bf0, b0, p_h0);

    // fused fold: Wa = diag(s0)*(W02@Wc), ba += t0@(W02@Wc)
    fold0_kernel<<<HH, HH, smf>>>(bn0w, bn0b, W02, Wc);
    bfrag_kernel<HH,HH><<<dim3(HH/8, HH/16), 32>>>(p_Wa, p_bfa);

    // hc = h0 @ Wa + ba   (fp16x2 output)
    gemm_tc<HH,HH,false,-1,true><<<TOT/128, 256, smA2>>>(p_h0, p_bfa, p_ba, p_hcp);

    if (fork) cudaStreamWaitEvent(0, g_side.eJoin, 0);   // join edge-build branch

    // SGC aggregate (+mask, relu, bnc stats)
    agg_kernel<<<TOT/8, 128>>>(nn);

    // fused fold bnc into W1 -> fragment table + bias (bb pre-seeded with b1)
    fold_bfrag_kernel<HH,HH><<<dim3(HH/8, HH/16), 32>>>(bncw, bncb, 1, W1, p_bfb, p_bb);

    // h2 = relu(h1 @ Wb + bb), bn1 stats fused
    gemm_tc<HH,HH,true,2,false><<<TOT/128, 256, smA2>>>(p_h1, p_bfb, p_bb, p_h2);

    // fused fold bn1 into W2 -> fragment table + bias (bo pre-seeded with b2)
    fold_bfrag_kernel<HH,FOUT><<<dim3(FOUT/8, HH/16), 32>>>(bn1w, bn1b, 2, W2, p_bfo, p_bo);

    // out = h2 @ Wo + bo
    gemm_tc<HH,FOUT,false,-1,false><<<TOT/128, 256, smA2>>>(p_h2, p_bfo, p_bo, out);
}

// round 14
// speedup vs baseline: 2.0427x; 1.0610x over previous
#include <cuda_runtime.h>
#include <cuda_fp16.h>
#include <cstdint>

#define BB   8
#define NN   8192
#define EE   262144
#define FIN  64
#define HH   128
#define FOUT 32
#define TOT  (BB*NN)   // 65536 rows total
#define CAP  128       // bucket capacity; deg ~ Poisson(32), max over 65K rows ~ 70

typedef unsigned long long ull;
typedef unsigned int uint;

// ---------------- device scratch (no allocations allowed) ----------------
__device__ uint  g_h0p[(size_t)TOT*(HH/2)];   // h0 as fp16x2 pairs
__device__ uint  g_hcp[(size_t)TOT*(HH/2)];   // hc as fp16x2 pairs
__device__ uint  g_h1p[(size_t)TOT*(HH/2)];   // h1 as fp16x2 pairs
__device__ float g_h2[(size_t)TOT*HH];
__device__ int   g_cnt[TOT];
__device__ uint  g_bkt[(size_t)TOT*CAP];      // bucketed edges: [fp16 val | 16-bit col]
__device__ float g_stat[6*HH];                // [stage][sum|sumsq][H], stages 0..2
__device__ float g_Wa[HH*HH];
__device__ float g_ba[HH];
__device__ float g_bb[HH];
__device__ float g_bo[FOUT];
// fragment-order split-fp16 weight tables: uint4 {bh0,bh1,bl0,bl1} per (ntile,kstep,lane)
__device__ uint4 g_bf0[(HH/8)*(FIN/16)*32];   // W0:  K=64,  N=128
__device__ uint4 g_bfa[(HH/8)*(HH/16)*32];    // Wa:  K=128, N=128
__device__ uint4 g_bfb[(HH/8)*(HH/16)*32];    // Wb:  K=128, N=128
__device__ uint4 g_bfo[(FOUT/8)*(HH/16)*32];  // Wo:  K=128, N=32

// ---------------- side stream for fork-join overlap (created pre-main) -----------
struct SideCtx {
    cudaStream_t s = 0;
    cudaEvent_t  eFork = 0, eJoin = 0;
    bool ok = false;
    SideCtx() {
        ok = (cudaStreamCreateWithFlags(&s, cudaStreamNonBlocking) == cudaSuccess) &&
             (cudaEventCreateWithFlags(&eFork, cudaEventDisableTiming) == cudaSuccess) &&
             (cudaEventCreateWithFlags(&eJoin, cudaEventDisableTiming) == cudaSuccess);
    }
};
static SideCtx g_side;

__device__ __forceinline__ float2 h2f(uint p) {
    return __half22float2(*reinterpret_cast<__half2*>(&p));
}
__device__ __forceinline__ void mma16816(float* d, const uint* a, uint b0, uint b1) {
    asm volatile("mma.sync.aligned.m16n8k16.row.col.f32.f16.f16.f32 "
        "{%0,%1,%2,%3}, {%4,%5,%6,%7}, {%8,%9}, {%0,%1,%2,%3};\n"
        : "+f"(d[0]), "+f"(d[1]), "+f"(d[2]), "+f"(d[3])
        : "r"(a[0]), "r"(a[1]), "r"(a[2]), "r"(a[3]), "r"(b0), "r"(b1));
}
// BN affine coefficients from accumulated stats
__device__ __forceinline__ void bn_st(int stage, int f, const float* bnw, const float* bnb,
                                      float& s, float& t) {
    float cnt = (float)TOT;
    float sum = g_stat[stage*2*HH + f];
    float sq  = g_stat[stage*2*HH + HH + f];
    float m = sum / cnt;
    float v = sq / cnt - m*m;
    float inv = rsqrtf(v + 1e-5f);
    s = bnw[f] * inv;
    t = bnb[f] - m * s;
}

// ---------------- zero bucket counters (side branch, feeds scatter) ----------------
__global__ void zero_cnt_kernel()
{
    int gid = blockIdx.x * 256 + threadIdx.x;
    if (gid < TOT) g_cnt[gid] = 0;
}

// ---------------- stats zero + fused bias seeds (main branch, 1 block) -------------
__global__ void init_bias_kernel(const float* __restrict__ b02, const float* __restrict__ Wc,
                                 const float* __restrict__ bc,  const float* __restrict__ b1,
                                 const float* __restrict__ b2)
{
    int k = threadIdx.x;   // 128
    #pragma unroll
    for (int i = k; i < 6*HH; i += 128) g_stat[i] = 0.f;
    float s = bc[k];
    #pragma unroll 8
    for (int f = 0; f < HH; f++) s += b02[f] * Wc[f*HH + k];
    g_ba[k] = s;              // (b02 @ Wc + bc); fold0 adds t0 @ (W02@Wc)
    g_bb[k] = b1[k];          // fold_bfrag(1) adds t1 @ W1
    if (k < FOUT) g_bo[k] = b2[k];   // fold_bfrag(2) adds t2 @ W2
}

// ---------------- fused BN0-fold + W02@Wc: Wa[f,:] = s0[f]*(W02[f,:]@Wc) ------------
__global__ void fold0_kernel(const float* __restrict__ bnw, const float* __restrict__ bnb,
                             const float* __restrict__ W02, const float* __restrict__ Wc)
{
    extern __shared__ float sh[];               // [HH*HH] Wc + [HH] w02 row + 2
    float* Wcs = sh;
    float* row = sh + HH*HH;
    float* stp = sh + HH*HH + HH;
    int f = blockIdx.x, k = threadIdx.x;

    #pragma unroll 8
    for (int i = k; i < HH*HH/4; i += HH) ((float4*)Wcs)[i] = ((const float4*)Wc)[i];
    row[k] = W02[f*HH + k];
    if (k == 0) { float s, t; bn_st(0, f, bnw, bnb, s, t); stp[0] = s; stp[1] = t; }
    __syncthreads();

    float m = 0.f;
    #pragma unroll 8
    for (int j = 0; j < HH; j++) m = fmaf(row[j], Wcs[j*HH + k], m);
    g_Wa[f*HH + k] = stp[0] * m;
    atomicAdd(&g_ba[k], stp[1] * m);
}

// ---------------- weight -> split-fp16 mma B-fragment table ----------------
template<int K, int N>
__global__ void bfrag_kernel(const float* __restrict__ W, uint4* __restrict__ out)
{
    constexpr int KS = K/16;
    int nt = blockIdx.x, ks = blockIdx.y, lane = threadIdx.x;
    int g = lane >> 2, t = lane & 3;
    int n = nt*8 + g, k0 = ks*16 + 2*t;
    float w00 = W[(k0+0)*N + n], w01 = W[(k0+1)*N + n];
    float w10 = W[(k0+8)*N + n], w11 = W[(k0+9)*N + n];
    __half h00 = __float2half_rn(w00), h01 = __float2half_rn(w01);
    __half h10 = __float2half_rn(w10), h11 = __float2half_rn(w11);
    __half l00 = __float2half_rn(w00 - __half2float(h00));
    __half l01 = __float2half_rn(w01 - __half2float(h01));
    __half l10 = __float2half_rn(w10 - __half2float(h10));
    __half l11 = __float2half_rn(w11 - __half2float(h11));
    __half2 bh0 = __halves2half2(h00, h01), bh1 = __halves2half2(h10, h11);
    __half2 bl0 = __halves2half2(l00, l01), bl1 = __halves2half2(l10, l11);
    uint4 v;
    v.x = *(uint*)&bh0; v.y = *(uint*)&bh1; v.z = *(uint*)&bl0; v.w = *(uint*)&bl1;
    out[(nt*KS + ks)*32 + lane] = v;
}

// ---------------- fused BN-fold + split-fp16 fragment build + bias ----------------
template<int K, int N>
__global__ void fold_bfrag_kernel(const float* __restrict__ bnw, const float* __restrict__ bnb,
                                  int stage, const float* __restrict__ W,
                                  uint4* __restrict__ out, float* __restrict__ bias)
{
    constexpr int KS = K/16;
    int nt = blockIdx.x, ks = blockIdx.y, lane = threadIdx.x;
    int g = lane >> 2, t = lane & 3;
    int n = nt*8 + g, k0 = ks*16 + 2*t;
    float s0,t0,s1,t1,s2,t2,s3,t3;
    bn_st(stage, k0+0, bnw, bnb, s0, t0);
    bn_st(stage, k0+1, bnw, bnb, s1, t1);
    bn_st(stage, k0+8, bnw, bnb, s2, t2);
    bn_st(stage, k0+9, bnw, bnb, s3, t3);
    float m00 = W[(k0+0)*N + n], m01 = W[(k0+1)*N + n];
    float m10 = W[(k0+8)*N + n], m11 = W[(k0+9)*N + n];
    float w00 = s0*m00, w01 = s1*m01, w10 = s2*m10, w11 = s3*m11;
    __half h00 = __float2half_rn(w00), h01 = __float2half_rn(w01);
    __half h10 = __float2half_rn(w10), h11 = __float2half_rn(w11);
    __half l00 = __float2half_rn(w00 - __half2float(h00));
    __half l01 = __float2half_rn(w01 - __half2float(h01));
    __half l10 = __float2half_rn(w10 - __half2float(h10));
    __half l11 = __float2half_rn(w11 - __half2float(h11));
    __half2 bh0 = __halves2half2(h00, h01), bh1 = __halves2half2(h10, h11);
    __half2 bl0 = __halves2half2(l00, l01), bl1 = __halves2half2(l10, l11);
    uint4 v;
    v.x = *(uint*)&bh0; v.y = *(uint*)&bh1; v.z = *(uint*)&bl0; v.w = *(uint*)&bl1;
    out[(nt*KS + ks)*32 + lane] = v;
    // bias contribution, reduced over the 4 t-lanes sharing column n
    float bc = t0*m00 + t1*m01 + t2*m10 + t3*m11;
    bc += __shfl_xor_sync(0xffffffffu, bc, 1);
    bc += __shfl_xor_sync(0xffffffffu, bc, 2);
    if (t == 0) atomicAdd(&bias[n], bc);
}

// ---------------- single-pass bucketed edge build (4 edges/thread) ----------------
__global__ void scatter_kernel(const int* __restrict__ rows, const int* __restrict__ cols,
                               const float* __restrict__ vals)
{
    int gid = blockIdx.x * 256 + threadIdx.x;        // grid covers (BB*EE)/4
    int e0 = gid * 4;
    if (e0 >= BB*EE) return;
    int base = (e0 >> 18) * NN;                      // 4 edges never cross a batch
    int4   r = *(const int4*)(rows + e0);
    int4   c = *(const int4*)(cols + e0);
    float4 v = *(const float4*)(vals + e0);
    int i0 = base + r.x, i1 = base + r.y, i2 = base + r.z, i3 = base + r.w;
    int p0 = atomicAdd(&g_cnt[i0], 1);
    int p1 = atomicAdd(&g_cnt[i1], 1);
    int p2 = atomicAdd(&g_cnt[i2], 1);
    int p3 = atomicAdd(&g_cnt[i3], 1);
    uint h0 = (uint)__half_as_ushort(__float2half_rn(v.x));
    uint h1 = (uint)__half_as_ushort(__float2half_rn(v.y));
    uint h2 = (uint)__half_as_ushort(__float2half_rn(v.z));
    uint h3 = (uint)__half_as_ushort(__float2half_rn(v.w));
    if (p0 < CAP) g_bkt[(size_t)i0*CAP + p0] = (h0 << 16) | (uint)c.x;
    if (p1 < CAP) g_bkt[(size_t)i1*CAP + p1] = (h1 << 16) | (uint)c.y;
    if (p2 < CAP) g_bkt[(size_t)i2*CAP + p2] = (h2 << 16) | (uint)c.z;
    if (p3 < CAP) g_bkt[(size_t)i3*CAP + p3] = (h3 << 16) | (uint)c.w;
}

// ---------------- SpMM aggregate (fp16 gather) + norm + mask + relu + bnc stats --------
// h1 written as fp16x2 pairs.
__global__ void agg_kernel(const int* __restrict__ nn)
{
    __shared__ float s_ls[HH], s_lq[HH];
    int tid = threadIdx.x, w = tid >> 5, lane = tid & 31;
    for (int i = tid; i < HH; i += 128) { s_ls[i] = 0.f; s_lq[i] = 0.f; }
    __syncthreads();

    float ls[4] = {0,0,0,0}, lq[4] = {0,0,0,0};
    #pragma unroll 1
    for (int ri = 0; ri < 2; ri++) {
        int idx = blockIdx.x * 8 + ri*4 + w;
        int b = idx >> 13, r = idx & (NN - 1);
        int len = min(g_cnt[idx], CAP);
        const uint2* hcb = (const uint2*)g_hcp + (size_t)b*NN*32;
        const uint*  ep  = g_bkt + (size_t)idx*CAP;

        float a0=0.f, a1=0.f, a2=0.f, a3=0.f, ds=0.f;
        for (int e0 = 0; e0 < len; e0 += 32) {
            uint my = (e0 + lane < len) ? ep[e0 + lane] : 0u;
            int m = min(32, len - e0);
            int t = 0;
            for (; t + 2 <= m; t += 2) {
                uint ea = __shfl_sync(0xffffffffu, my, t);
                uint eb = __shfl_sync(0xffffffffu, my, t+1);
                float va = __half2float(__ushort_as_half((unsigned short)(ea >> 16)));
                float vb = __half2float(__ushort_as_half((unsigned short)(eb >> 16)));
                uint2 ha = hcb[(size_t)(ea & 0xFFFFu)*32 + lane];
                uint2 hb = hcb[(size_t)(eb & 0xFFFFu)*32 + lane];
                float2 fa0 = h2f(ha.x), fa1 = h2f(ha.y);
                float2 fb0 = h2f(hb.x), fb1 = h2f(hb.y);
                a0 = fmaf(va, fa0.x, a0);  a1 = fmaf(va, fa0.y, a1);
                a2 = fmaf(va, fa1.x, a2);  a3 = fmaf(va, fa1.y, a3);
                a0 = fmaf(vb, fb0.x, a0);  a1 = fmaf(vb, fb0.y, a1);
                a2 = fmaf(vb, fb1.x, a2);  a3 = fmaf(vb, fb1.y, a3);
                ds += va + vb;
            }
            if (t < m) {
                uint ea = __shfl_sync(0xffffffffu, my, t);
                float va = __half2float(__ushort_as_half((unsigned short)(ea >> 16)));
                uint2 ha = hcb[(size_t)(ea & 0xFFFFu)*32 + lane];
                float2 fa0 = h2f(ha.x), fa1 = h2f(ha.y);
                a0 = fmaf(va, fa0.x, a0);  a1 = fmaf(va, fa0.y, a1);
                a2 = fmaf(va, fa1.x, a2);  a3 = fmaf(va, fa1.y, a3);
                ds += va;
            }
        }
        float inv = 1.f / fmaxf(ds, 1.f);
        bool dead = (r >= nn[b]);
        float o0 = dead ? 0.f : fmaxf(a0*inv, 0.f);
        float o1 = dead ? 0.f : fmaxf(a1*inv, 0.f);
        float o2 = dead ? 0.f : fmaxf(a2*inv, 0.f);
        float o3 = dead ? 0.f : fmaxf(a3*inv, 0.f);
        __half2 q0 = __floats2half2_rn(o0, o1);
        __half2 q1 = __floats2half2_rn(o2, o3);
        uint2 qq; qq.x = *(uint*)&q0; qq.y = *(uint*)&q1;
        ((uint2*)g_h1p)[(size_t)idx*32 + lane] = qq;
        ls[0]+=o0; lq[0]+=o0*o0;  ls[1]+=o1; lq[1]+=o1*o1;
        ls[2]+=o2; lq[2]+=o2*o2;  ls[3]+=o3; lq[3]+=o3*o3;
    }
    #pragma unroll
    for (int q = 0; q < 4; q++) {
        atomicAdd(&s_ls[lane*4+q], ls[q]);
        atomicAdd(&s_lq[lane*4+q], lq[q]);
    }
    __syncthreads();
    for (int i = tid; i < HH; i += 128) {
        atomicAdd(&g_stat[1*2*HH + i],      s_ls[i]);
        atomicAdd(&g_stat[1*2*HH + HH + i], s_lq[i]);
    }
}

// ---------------- tensor-core GEMM ----------------
// IN16=false: A fp32, 3-term split (Ah@Wh + Ah@Wl + Al@Wh), error ~ fp32.
// IN16=true:  A fp16 (stored), 2-term (A@Wh + A@Wl).
template<int K, int NC, bool RELU, int STAGE, bool OUT16, bool IN16>
__global__ __launch_bounds__(256, 2)
void gemm_tc(const void* __restrict__ Av, const uint4* __restrict__ BF,
             const float* __restrict__ bias, void* __restrict__ Cv)
{
    constexpr int KS  = K / 16;
    constexpr int WM  = (NC >= 128) ? 4 : 8;    // warps along M
    constexpr int WN  = 8 / WM;                 // warps along N
    constexpr int MF  = 128 / WM / 16;          // m16 frags per warp (2 or 1)
    constexpr int NF  = NC / WN / 8;            // n8 frags per warp (8 or 4)
    constexpr int AST = K + 8;                  // half stride: 2*AST % 128B == 16

    extern __shared__ __half sh2[];
    __half* Ah = sh2;                           // [128][AST]
    __half* Al = sh2 + (IN16 ? 0 : 128*AST);    // unused alias when IN16
    __shared__ float s_ls[HH], s_lq[HH];

    int tid = threadIdx.x;
    size_t row0 = (size_t)blockIdx.x * 128;

    if (IN16) {
        // A already fp16: straight copy into smem
        const uint4* Ag = (const uint4*)((const __half*)Av + row0*K);
        #pragma unroll 4
        for (int i = tid; i < 128*K/8; i += 256) {
            uint4 v = Ag[i];
            int r = (i*8)/K, c = (i*8)%K;
            *(uint4*)&Ah[r*AST + c] = v;
        }
    } else {
        // load A tile fp32, split into hi/lo fp16
        const float4* Ag = (const float4*)((const float*)Av + row0*K);
        #pragma unroll 4
        for (int i = tid; i < 128*K/4; i += 256) {
            float4 v = Ag[i];
            int r = (i*4)/K, c = (i*4)%K;
            __half h0 = __float2half_rn(v.x), h1 = __float2half_rn(v.y);
            __half h2v = __float2half_rn(v.z), h3 = __float2half_rn(v.w);
            __half* ap = Ah + r*AST + c;
            ap[0] = h0; ap[1] = h1; ap[2] = h2v; ap[3] = h3;
            __half* lp = Al + r*AST + c;
            lp[0] = __float2half_rn(v.x - __half2float(h0));
            lp[1] = __float2half_rn(v.y - __half2float(h1));
            lp[2] = __float2half_rn(v.z - __half2float(h2v));
            lp[3] = __float2half_rn(v.w - __half2float(h3));
        }
    }
    if (STAGE >= 0) for (int i = tid; i < HH; i += 256) { s_ls[i] = 0.f; s_lq[i] = 0.f; }
    __syncthreads();

    int wid = tid >> 5, lane = tid & 31;
    int wm = wid % WM, wn = wid / WM;
    int g = lane >> 2, t = lane & 3;

    float acc[MF][NF][4];
    #pragma unroll
    for (int mf = 0; mf < MF; mf++)
        #pragma unroll
        for (int nf = 0; nf < NF; nf++)
            #pragma unroll
            for (int q = 0; q < 4; q++) acc[mf][nf][q] = 0.f;

    const __half* AhB = Ah + (wm*MF*16)*AST;
    const __half* AlB = Al + (wm*MF*16)*AST;

    #pragma unroll
    for (int ks = 0; ks < KS; ks++) {
        uint ah[MF][4], al[MF][4];
        #pragma unroll
        for (int mf = 0; mf < MF; mf++) {
            int r0 = mf*16 + g, r1 = r0 + 8;
            int c0 = ks*16 + 2*t, c1 = c0 + 8;
            ah[mf][0] = *(const uint*)(AhB + r0*AST + c0);
            ah[mf][1] = *(const uint*)(AhB + r1*AST + c0);
            ah[mf][2] = *(const uint*)(AhB + r0*AST + c1);
            ah[mf][3] = *(const uint*)(AhB + r1*AST + c1);
            if (!IN16) {
                al[mf][0] = *(const uint*)(AlB + r0*AST + c0);
                al[mf][1] = *(const uint*)(AlB + r1*AST + c0);
                al[mf][2] = *(const uint*)(AlB + r0*AST + c1);
                al[mf][3] = *(const uint*)(AlB + r1*AST + c1);
            }
        }
        #pragma unroll
        for (int nf = 0; nf < NF; nf++) {
            int nt = wn*NF + nf;
            uint4 b = BF[(nt*KS + ks)*32 + lane];
            #pragma unroll
            for (int mf = 0; mf < MF; mf++) {
                mma16816(acc[mf][nf], ah[mf], b.x, b.y);       // A(h) @ Wh
                mma16816(acc[mf][nf], ah[mf], b.z, b.w);       // A(h) @ Wl
                if (!IN16) mma16816(acc[mf][nf], al[mf], b.x, b.y);  // Al @ Wh
            }
        }
    }

    // epilogue: bias, relu, store, stats
    #pragma unroll
    for (int nf = 0; nf < NF; nf++) {
        int c = wn*NF*8 + nf*8 + 2*t;
        float b0v = bias[c], b1v = bias[c+1];
        float ls0 = 0.f, lq0 = 0.f, ls1 = 0.f, lq1 = 0.f;
        #pragma unroll
        for (int mf = 0; mf < MF; mf++) {
            float v00 = acc[mf][nf][0] + b0v, v01 = acc[mf][nf][1] + b1v;
            float v10 = acc[mf][nf][2] + b0v, v11 = acc[mf][nf][3] + b1v;
            if (RELU) {
                v00 = fmaxf(v00, 0.f); v01 = fmaxf(v01, 0.f);
                v10 = fmaxf(v10, 0.f); v11 = fmaxf(v11, 0.f);
            }
            size_t r0 = row0 + wm*MF*16 + mf*16 + g, r1 = r0 + 8;
            if (OUT16) {
                __half2 p0 = __float22half2_rn(make_float2(v00, v01));
                __half2 p1 = __float22half2_rn(make_float2(v10, v11));
                ((uint*)Cv)[r0*(NC/2) + c/2] = *(uint*)&p0;
                ((uint*)Cv)[r1*(NC/2) + c/2] = *(uint*)&p1;
            } else {
                *(float2*)&((float*)Cv)[r0*NC + c] = make_float2(v00, v01);
                *(float2*)&((float*)Cv)[r1*NC + c] = make_float2(v10, v11);
            }
            if (STAGE >= 0) {
                ls0 += v00 + v10; lq0 += v00*v00 + v10*v10;
                ls1 += v01 + v11; lq1 += v01*v01 + v11*v11;
            }
        }
        if (STAGE >= 0) {
            #pragma unroll
            for (int o = 4; o <= 16; o <<= 1) {
                ls0 += __shfl_xor_sync(0xffffffffu, ls0, o);
                lq0 += __shfl_xor_sync(0xffffffffu, lq0, o);
                ls1 += __shfl_xor_sync(0xffffffffu, ls1, o);
                lq1 += __shfl_xor_sync(0xffffffffu, lq1, o);
            }
            if (lane < 4) {
                atomicAdd(&s_ls[c], ls0); atomicAdd(&s_lq[c], lq0);
                atomicAdd(&s_ls[c+1], ls1); atomicAdd(&s_lq[c+1], lq1);
            }
        }
    }

    if (STAGE >= 0) {
        __syncthreads();
        for (int i = tid; i < NC; i += 256) {
            atomicAdd(&g_stat[STAGE*2*HH + i],      s_ls[i]);
            atomicAdd(&g_stat[STAGE*2*HH + HH + i], s_lq[i]);
        }
    }
}

// ---------------- host launcher ----------------
extern "C" void kernel_launch(void* const* d_in, const int* in_sizes, int n_in,
                              void* d_out, int out_size)
{
    const float* x    = (const float*)d_in[0];
    const int*   erow = (const int*)  d_in[1];
    const int*   ecol = (const int*)  d_in[2];
    const float* evl  = (const float*)d_in[3];
    const int*   nn   = (const int*)  d_in[4];
    const float* W0   = (const float*)d_in[5];
    const float* b0   = (const float*)d_in[6];
    const float* W02  = (const float*)d_in[7];
    const float* b02  = (const float*)d_in[8];
    const float* Wc   = (const float*)d_in[9];
    const float* bc   = (const float*)d_in[10];
    const float* W1   = (const float*)d_in[11];
    const float* b1   = (const float*)d_in[12];
    const float* W2   = (const float*)d_in[13];
    const float* b2   = (const float*)d_in[14];
    const float* bn0w = (const float*)d_in[15];
    const float* bn0b = (const float*)d_in[16];
    const float* bncw = (const float*)d_in[17];
    const float* bncb = (const float*)d_in[18];
    const float* bn1w = (const float*)d_in[19];
    const float* bn1b = (const float*)d_in[20];
    float* out = (float*)d_out;

    float *p_h2, *p_Wa, *p_ba, *p_bb, *p_bo;
    uint  *p_h0p, *p_hcp, *p_h1p;
    uint4 *p_bf0, *p_bfa, *p_bfb, *p_bfo;
    cudaGetSymbolAddress((void**)&p_h0p, g_h0p);
    cudaGetSymbolAddress((void**)&p_hcp, g_hcp);
    cudaGetSymbolAddress((void**)&p_h1p, g_h1p);
    cudaGetSymbolAddress((void**)&p_h2,  g_h2);
    cudaGetSymbolAddress((void**)&p_Wa,  g_Wa);
    cudaGetSymbolAddress((void**)&p_ba,  g_ba);
    cudaGetSymbolAddress((void**)&p_bb,  g_bb);
    cudaGetSymbolAddress((void**)&p_bo,  g_bo);
    cudaGetSymbolAddress((void**)&p_bf0, g_bf0);
    cudaGetSymbolAddress((void**)&p_bfa, g_bfa);
    cudaGetSymbolAddress((void**)&p_bfb, g_bfb);
    cudaGetSymbolAddress((void**)&p_bfo, g_bfo);

    const size_t sm0  = (size_t)2 * 128 * (FIN + 8) * sizeof(__half);   // K=64, split A
    const size_t sm16 = (size_t)    128 * (HH  + 8) * sizeof(__half);   // K=128, fp16 A
    const size_t sm32 = (size_t)2 * 128 * (HH  + 8) * sizeof(__half);   // K=128, split A
    const size_t smf  = ((size_t)HH*HH + HH + 2) * sizeof(float);
    cudaFuncSetAttribute(gemm_tc<FIN,HH,true,0,true,false>,     cudaFuncAttributeMaxDynamicSharedMemorySize, (int)sm0);
    cudaFuncSetAttribute(gemm_tc<HH,HH,false,-1,true,true>,     cudaFuncAttributeMaxDynamicSharedMemorySize, (int)sm16);
    cudaFuncSetAttribute(gemm_tc<HH,HH,true,2,false,true>,      cudaFuncAttributeMaxDynamicSharedMemorySize, (int)sm16);
    cudaFuncSetAttribute(gemm_tc<HH,FOUT,false,-1,false,false>, cudaFuncAttributeMaxDynamicSharedMemorySize, (int)sm32);
    cudaFuncSetAttribute(fold0_kernel, cudaFuncAttributeMaxDynamicSharedMemorySize, (int)smf);

    const int EG = (BB*EE/4 + 255) / 256;   // grid for 4-edge-per-thread kernels
    bool fork = g_side.ok;

    if (fork) {
        // fork immediately: bucket zero + edge build on side stream
        cudaEventRecord(g_side.eFork, 0);
        cudaStreamWaitEvent(g_side.s, g_side.eFork, 0);
        zero_cnt_kernel<<<TOT/256, 256, 0, g_side.s>>>();
        scatter_kernel<<<EG, 256, 0, g_side.s>>>(erow, ecol, evl);
        cudaEventRecord(g_side.eJoin, g_side.s);
    } else {
        zero_cnt_kernel<<<TOT/256, 256>>>();
        scatter_kernel<<<EG, 256>>>(erow, ecol, evl);
    }

    // main chain
    init_bias_kernel<<<1, 128>>>(b02, Wc, bc, b1, b2);
    bfrag_kernel<FIN,HH><<<dim3(HH/8, FIN/16), 32>>>(W0, p_bf0);

    // h0 = relu(x@W0 + b0) with bn0 stats  (fp16 out)
    gemm_tc<FIN,HH,true,0,true,false><<<TOT/128, 256, sm0>>>(x, p_bf0, b0, p_h0p);

    // fused fold: Wa = diag(s0)*(W02@Wc), ba += t0@(W02@Wc)
    fold0_kernel<<<HH, HH, smf>>>(bn0w, bn0b, W02, Wc);
    bfrag_kernel<HH,HH><<<dim3(HH/8, HH/16), 32>>>(p_Wa, p_bfa);

    // hc = h0 @ Wa + ba   (fp16 in, fp16 out, 2-term)
    gemm_tc<HH,HH,false,-1,true,true><<<TOT/128, 256, sm16>>>(p_h0p, p_bfa, p_ba, p_hcp);

    if (fork) cudaStreamWaitEvent(0, g_side.eJoin, 0);   // join edge-build branch

    // SGC aggregate (+mask, relu, bnc stats) -> h1 fp16
    agg_kernel<<<TOT/8, 128>>>(nn);

    // fused fold bnc into W1 -> fragment table + bias (bb pre-seeded with b1)
    fold_bfrag_kernel<HH,HH><<<dim3(HH/8, HH/16), 32>>>(bncw, bncb, 1, W1, p_bfb, p_bb);

    // h2 = relu(h1 @ Wb + bb), bn1 stats fused  (fp16 in, fp32 out, 2-term)
    gemm_tc<HH,HH,true,2,false,true><<<TOT/128, 256, sm16>>>(p_h1p, p_bfb, p_bb, p_h2);

    // fused fold bn1 into W2 -> fragment table + bias (bo pre-seeded with b2)
    fold_bfrag_kernel<HH,FOUT><<<dim3(FOUT/8, HH/16), 32>>>(bn1w, bn1b, 2, W2, p_bfo, p_bo);

    // out = h2 @ Wo + bo   (fp32 in 3-term, fp32 out)
    gemm_tc<HH,FOUT,false,-1,false,false><<<TOT/128, 256, sm32>>>(p_h2, p_bfo, p_bo, out);
}